// round 11
// baseline (speedup 1.0000x reference)
#include <cuda_runtime.h>
#include <cuda_fp16.h>
#include <math.h>

// ============================================================================
// SurfaceCodeGNN: 4-layer GCN + BN/SiLU + mean-pool + MLP head
// N=100000, E=600000, H=128, G=256
//
// Round 11: gather processes 2 nodes per warp iteration (2x outstanding
// loads on the index->row dependency chain); probe is now a quarter-size
// dummy gather (4th launch) so ncu finally shows the gather roofline.
// GEMM kept at R10 config (512 thr, ldmatrix, pre-transposed fp16 W).
// ============================================================================

#define H 128
#define MAXN 100352
#define MAXE 1200000
#define MAXG 1024

__device__ __half g_th[(size_t)MAXN * H];    // pre-scaled messages dis[r]*t[r]
__device__ float  g_agg[(size_t)MAXN * H];   // gather output (pre-BN)
__device__ __half g_wt[3 * H * H];           // W transposed [layer][n][k] fp16
__device__ float  g_s[MAXN];
__device__ float  g_sx[MAXN];                // dis[i]*x[i]; row N stays 0
__device__ float  g_dis[MAXN];
__device__ int    g_indeg[MAXN];
__device__ int    g_rowptr[MAXN];
__device__ int    g_cursor[MAXN];
__device__ int    g_csr[MAXE];
__device__ int    g_ctr;
__device__ double g_dsum[H], g_dsq[H];
__device__ double g_dsumD[H], g_dsqD[H];     // probe stat sinks
__device__ double g_sstats[2];
__device__ float  g_scale[H], g_shift[H];
__device__ float  g_C0[H], g_B0[H];
__device__ float  g_pool[MAXG * H];
__device__ float  g_cnt[MAXG];
__device__ int    g_is64;

static __device__ __forceinline__ float silu_f(float x) {
    float e = __expf(-x);
    return __fdividef(x, 1.0f + e);
}

// silu via single-MUFU hw tanh: x*sigmoid(x) = 0.5x + 0.5x*tanh(x/2)
static __device__ __forceinline__ float silu_t(float x) {
    float t;
    asm("tanh.approx.f32 %0, %1;" : "=f"(t) : "f"(0.5f * x));
    return fmaf(0.5f * x, t, 0.5f * x);
}

static __device__ __forceinline__ int ldidx(const void* p, long long i, int is64) {
    return ((const int*)p)[is64 ? 2 * i : i];
}

// ---------------------------------------------------------------------------
// init: zero indeg/pool/cnt/counters; detect index dtype
// ---------------------------------------------------------------------------
__global__ void init_kernel(const void* ei, int N, int GP, int G) {
    int i = blockIdx.x * blockDim.x + threadIdx.x;
    if (i < N) g_indeg[i] = 0;
    if (i < GP) g_pool[i] = 0.f;
    if (i < G) g_cnt[i] = 0.f;
    if (i == 0) {
        g_ctr = 0;
        g_sstats[0] = 0.0;
        g_sstats[1] = 0.0;
    }
    if (blockIdx.x == 0 && threadIdx.x < 32) {
        int any = 0;
        const int* p = (const int*)ei;
        for (int k = threadIdx.x; k < 64; k += 32)
            if (p[2 * k + 1] != 0) any = 1;
        any = __any_sync(0xffffffffu, any);
        if (threadIdx.x == 0) g_is64 = any ? 0 : 1;
    }
}

__global__ void indeg_count_kernel(const void* ei, int E) {
    int e = blockIdx.x * blockDim.x + threadIdx.x;
    if (e >= E) return;
    int is64 = g_is64;
    int c = ldidx(ei, (long long)E + e, is64);
    atomicAdd(&g_indeg[c], 1);
}

// ---------------------------------------------------------------------------
// wprep: transpose/convert all 3 GCN weights to fp16 n-major (once)
// ---------------------------------------------------------------------------
__global__ void wprep_kernel(const float* __restrict__ Ws) {
    int i = blockIdx.x * blockDim.x + threadIdx.x;
    if (i >= 3 * H * H) return;
    int layer = i >> 14;
    int rem = i & 16383;
    int k = rem >> 7, n = rem & 127;
    g_wt[layer * H * H + n * H + k] = __float2half_rn(Ws[i]);
}

// ---------------------------------------------------------------------------
// assign: dis, sx = dis*x, 4-aligned CSR segment alloc (pads -> dummy N)
// ---------------------------------------------------------------------------
__global__ void assign_kernel(const float* __restrict__ x, int N) {
    int i = blockIdx.x * blockDim.x + threadIdx.x;
    int lane = threadIdx.x & 31;
    int deg = (i < N) ? g_indeg[i] : 0;
    int degPad = (deg + 3) & ~3;
    int v = degPad;
#pragma unroll
    for (int off = 1; off < 32; off <<= 1) {
        int t = __shfl_up_sync(0xffffffffu, v, off);
        if (lane >= off) v += t;
    }
    int warpTot = __shfl_sync(0xffffffffu, v, 31);
    int base = 0;
    if (lane == 31) base = atomicAdd(&g_ctr, warpTot);
    base = __shfl_sync(0xffffffffu, base, 31);
    if (i < N) {
        int rp = base + v - degPad;
        g_rowptr[i] = rp;
        g_cursor[i] = rp;
        for (int p = deg; p < degPad; p++) g_csr[rp + p] = N;  // zero row
        float dis = rsqrtf((float)(deg + 1));  // +1 self loop
        g_dis[i] = dis;
        g_sx[i] = dis * x[i];
    }
}

__global__ void fill_kernel(const void* ei, int E) {
    int e = blockIdx.x * blockDim.x + threadIdx.x;
    if (e >= E) return;
    int is64 = g_is64;
    int r = ldidx(ei, e, is64);
    int c = ldidx(ei, (long long)E + e, is64);
    int p = atomicAdd(&g_cursor[c], 1);
    g_csr[p] = r;
}

// ---------------------------------------------------------------------------
// layer 0: s[c] = dis[c]*(sx[c] + sum_e sx[r]), + stats (pads add 0)
// ---------------------------------------------------------------------------
__global__ void layer0_kernel(int N) {
    int i = blockIdx.x * blockDim.x + threadIdx.x;
    float sum = 0.f, sq = 0.f;
    if (i < N) {
        int beg = g_rowptr[i];
        int cnt4 = (g_indeg[i] + 3) >> 2;
        float acc = g_sx[i];
        for (int e = 0; e < cnt4; e++) {
            int4 r4 = __ldg((const int4*)(g_csr + beg + e * 4));
            acc += __ldg(&g_sx[r4.x]) + __ldg(&g_sx[r4.y]) +
                   __ldg(&g_sx[r4.z]) + __ldg(&g_sx[r4.w]);
        }
        acc *= g_dis[i];
        g_s[i] = acc;
        sum = acc;
        sq = acc * acc;
    }
    __shared__ float sa[256], sb[256];
    sa[threadIdx.x] = sum;
    sb[threadIdx.x] = sq;
    __syncthreads();
    for (int off = 128; off > 0; off >>= 1) {
        if (threadIdx.x < off) {
            sa[threadIdx.x] += sa[threadIdx.x + off];
            sb[threadIdx.x] += sb[threadIdx.x + off];
        }
        __syncthreads();
    }
    if (threadIdx.x == 0) {
        atomicAdd(&g_sstats[0], (double)sa[0]);
        atomicAdd(&g_sstats[1], (double)sb[0]);
    }
}

__global__ void coef0_kernel(const float* __restrict__ W0,
                             const float* __restrict__ gamma0,
                             const float* __restrict__ beta0, int N) {
    int t = threadIdx.x;
    if (t >= H) return;
    g_dsum[t] = 0.0;
    g_dsq[t] = 0.0;
    double mu = g_sstats[0] / N;
    double var = g_sstats[1] / N - mu * mu;
    float w = W0[t];
    float inv = rsqrtf((float)var * w * w + 1e-5f);
    float c = w * inv * gamma0[t];
    g_C0[t] = c;
    g_B0[t] = beta0[t] - (float)mu * c;
}

// ---------------------------------------------------------------------------
// Tensor-core GEMM: th = half( dis[n] * (silu_bn(A) @ W) )
// 512 threads, 16 warps; warp w -> rows [(w>>1)*16,+16), cols [(w&1)*64,+64).
// ---------------------------------------------------------------------------
#define ASTRIDE 136  // halfs per padded row (272B -> ldmatrix conflict-free)
#define GEMM_SMEM_BYTES (34816 * 2 + 1024)

static __device__ __forceinline__ void mma16816(float& c0, float& c1, float& c2,
                                                float& c3, unsigned a0, unsigned a1,
                                                unsigned a2, unsigned a3,
                                                unsigned b0, unsigned b1) {
    asm volatile(
        "mma.sync.aligned.m16n8k16.row.col.f32.f16.f16.f32 "
        "{%0,%1,%2,%3}, {%4,%5,%6,%7}, {%8,%9}, {%0,%1,%2,%3};"
        : "+f"(c0), "+f"(c1), "+f"(c2), "+f"(c3)
        : "r"(a0), "r"(a1), "r"(a2), "r"(a3), "r"(b0), "r"(b1));
}

static __device__ __forceinline__ void ldsm4(unsigned& r0, unsigned& r1,
                                             unsigned& r2, unsigned& r3,
                                             unsigned addr) {
    asm volatile(
        "ldmatrix.sync.aligned.m8n8.x4.shared.b16 {%0,%1,%2,%3}, [%4];"
        : "=r"(r0), "=r"(r1), "=r"(r2), "=r"(r3)
        : "r"(addr));
}

template <int MODE>
__global__ void __launch_bounds__(512, 2)
gemm_kernel(int layer, int N) {
    extern __shared__ char smraw[];
    __half* As = (__half*)smraw;                  // [128][ASTRIDE]
    __half* Wt = (__half*)(smraw + 34816);        // [128][ASTRIDE] (n-major)
    float* scs = (float*)(smraw + 69632);         // 128
    float* shs = scs + 128;                       // 128

    const float* SRC = (MODE == 0) ? g_s : g_agg;
    const float* sc = (MODE == 0) ? g_C0 : g_scale;
    const float* sh = (MODE == 0) ? g_B0 : g_shift;

    int tid = threadIdx.x;
    if (tid < H) { scs[tid] = sc[tid]; shs[tid] = sh[tid]; }
    __syncthreads();

    int rowBase = blockIdx.x * 128;

    // stage Wt: coalesced conflict-free copy of pre-transposed weights
    {
        const uint4* wsrc4 = (const uint4*)(g_wt + layer * H * H);
        uint4* wdst4 = (uint4*)Wt;
#pragma unroll
        for (int i = tid; i < 2048; i += 512) {
            int n = i >> 4, cc = i & 15;
            wdst4[n * 17 + cc] = wsrc4[i];  // 17 uint4 per padded row
        }
    }

    // stage A (BN+SiLU fused) in fp16
    for (int i = tid; i < 4096; i += 512) {
        int r = i >> 5, kq = (i & 31) * 4;
        int gr = rowBase + r;
        float4 pre;
        if (gr < N) {
            if (MODE == 0) {
                float xin = g_s[gr];
                pre.x = fmaf(xin, scs[kq + 0], shs[kq + 0]);
                pre.y = fmaf(xin, scs[kq + 1], shs[kq + 1]);
                pre.z = fmaf(xin, scs[kq + 2], shs[kq + 2]);
                pre.w = fmaf(xin, scs[kq + 3], shs[kq + 3]);
            } else {
                float4 xin = __ldg((const float4*)(SRC + (size_t)gr * H + kq));
                pre.x = fmaf(xin.x, scs[kq + 0], shs[kq + 0]);
                pre.y = fmaf(xin.y, scs[kq + 1], shs[kq + 1]);
                pre.z = fmaf(xin.z, scs[kq + 2], shs[kq + 2]);
                pre.w = fmaf(xin.w, scs[kq + 3], shs[kq + 3]);
            }
            pre.x = silu_t(pre.x);
            pre.y = silu_t(pre.y);
            pre.z = silu_t(pre.z);
            pre.w = silu_t(pre.w);
        } else {
            pre = make_float4(0.f, 0.f, 0.f, 0.f);
        }
        __half2* dst = (__half2*)(As + r * ASTRIDE + kq);
        dst[0] = __floats2half2_rn(pre.x, pre.y);
        dst[1] = __floats2half2_rn(pre.z, pre.w);
    }
    __syncthreads();

    int warp = tid >> 5, lane = tid & 31;
    int g = lane >> 2, tig = lane & 3;
    int rbase = (warp >> 1) * 16;
    int colbase = (warp & 1) * 64;

    unsigned asu = (unsigned)__cvta_generic_to_shared(As);
    unsigned wtu = (unsigned)__cvta_generic_to_shared(Wt);
    int rowA = rbase + ((lane >> 3) & 1) * 8 + (lane & 7);
    int colA = (lane >> 4) * 8;
    unsigned aAddr = asu + (unsigned)((rowA * ASTRIDE + colA) * 2);
    int nrowB = colbase + (lane >> 4) * 8 + (lane & 7);
    int colB = ((lane >> 3) & 1) * 8;
    unsigned bAddr = wtu + (unsigned)((nrowB * ASTRIDE + colB) * 2);

    float c[8][4];
#pragma unroll
    for (int j = 0; j < 8; j++)
#pragma unroll
        for (int q = 0; q < 4; q++) c[j][q] = 0.f;

#pragma unroll
    for (int k0 = 0; k0 < 128; k0 += 16) {
        unsigned a0, a1, a2, a3;
        ldsm4(a0, a1, a2, a3, aAddr + k0 * 2);
#pragma unroll
        for (int jj = 0; jj < 4; jj++) {
            unsigned b0, b1, b2, b3;
            ldsm4(b0, b1, b2, b3,
                  bAddr + (unsigned)(jj * (16 * ASTRIDE * 2) + k0 * 2));
            mma16816(c[2 * jj][0], c[2 * jj][1], c[2 * jj][2], c[2 * jj][3],
                     a0, a1, a2, a3, b0, b1);
            mma16816(c[2 * jj + 1][0], c[2 * jj + 1][1], c[2 * jj + 1][2],
                     c[2 * jj + 1][3], a0, a1, a2, a3, b2, b3);
        }
    }

    // epilogue: th[row] = half(dis[row] * out), 64 cols per warp
    int r0 = rowBase + rbase + g;
    int r1 = r0 + 8;
    float d0 = (r0 < N) ? __ldg(&g_dis[r0]) : 0.f;
    float d1 = (r1 < N) ? __ldg(&g_dis[r1]) : 0.f;
    __half* out0 = g_th + (size_t)r0 * H + colbase + 2 * tig;
    __half* out1 = g_th + (size_t)r1 * H + colbase + 2 * tig;
#pragma unroll
    for (int j = 0; j < 8; j++) {
        if (r0 < N)
            *(__half2*)(out0 + j * 8) = __floats2half2_rn(c[j][0] * d0, c[j][1] * d0);
        if (r1 < N)
            *(__half2*)(out1 + j * 8) = __floats2half2_rn(c[j][2] * d1, c[j][3] * d1);
    }
}

// ---------------------------------------------------------------------------
// gather: agg[c] = dis[c]*(tS[c] + sum_e tS[r]);  BN stats fused.
// 2 nodes per warp per grid-stride iteration (warp-uniform guards, no
// divergence) -> 2 independent index streams, 8 row loads in flight.
// DUMMY=1: probe variant, stats to sink buffers.
// ---------------------------------------------------------------------------
template <int DUMMY>
__global__ void __launch_bounds__(256) gather_kernel(int N) {
    int lane = threadIdx.x & 31;
    int gw = blockIdx.x * 8 + (threadIdx.x >> 5);
    int nw = gridDim.x * 8;

    float4 lsum = make_float4(0.f, 0.f, 0.f, 0.f);
    float4 lsq = make_float4(0.f, 0.f, 0.f, 0.f);

    for (int c0 = gw; c0 < N; c0 += 2 * nw) {
        int c1 = c0 + nw;
        bool has1 = c1 < N;

        int beg0 = __ldg(&g_rowptr[c0]);
        int cnt0 = (__ldg(&g_indeg[c0]) + 3) >> 2;
        float dis0 = __ldg(&g_dis[c0]);
        int beg1 = 0, cnt1 = 0;
        float dis1 = 0.f;
        if (has1) {
            beg1 = __ldg(&g_rowptr[c1]);
            cnt1 = (__ldg(&g_indeg[c1]) + 3) >> 2;
            dis1 = __ldg(&g_dis[c1]);
        }

        uint2 sr0 = __ldg(((const uint2*)(g_th + (size_t)c0 * H)) + lane);
        float2 p0 = __half22float2(*(__half2*)&sr0.x);
        float2 p1 = __half22float2(*(__half2*)&sr0.y);
        float4 accA = make_float4(p0.x, p0.y, p1.x, p1.y);
        float4 accB = make_float4(0.f, 0.f, 0.f, 0.f);
        if (has1) {
            uint2 sr1 = __ldg(((const uint2*)(g_th + (size_t)c1 * H)) + lane);
            float2 q0 = __half22float2(*(__half2*)&sr1.x);
            float2 q1 = __half22float2(*(__half2*)&sr1.y);
            accB = make_float4(q0.x, q0.y, q1.x, q1.y);
        }

        int em = max(cnt0, cnt1);
        for (int e = 0; e < em; e++) {
            if (e < cnt0) {
                int4 r4 = __ldg((const int4*)(g_csr + beg0 + e * 4));
                uint2 a0 = __ldg(((const uint2*)(g_th + (size_t)r4.x * H)) + lane);
                uint2 a1 = __ldg(((const uint2*)(g_th + (size_t)r4.y * H)) + lane);
                uint2 a2 = __ldg(((const uint2*)(g_th + (size_t)r4.z * H)) + lane);
                uint2 a3 = __ldg(((const uint2*)(g_th + (size_t)r4.w * H)) + lane);
                float2 f;
                f = __half22float2(*(__half2*)&a0.x); accA.x += f.x; accA.y += f.y;
                f = __half22float2(*(__half2*)&a0.y); accA.z += f.x; accA.w += f.y;
                f = __half22float2(*(__half2*)&a1.x); accA.x += f.x; accA.y += f.y;
                f = __half22float2(*(__half2*)&a1.y); accA.z += f.x; accA.w += f.y;
                f = __half22float2(*(__half2*)&a2.x); accA.x += f.x; accA.y += f.y;
                f = __half22float2(*(__half2*)&a2.y); accA.z += f.x; accA.w += f.y;
                f = __half22float2(*(__half2*)&a3.x); accA.x += f.x; accA.y += f.y;
                f = __half22float2(*(__half2*)&a3.y); accA.z += f.x; accA.w += f.y;
            }
            if (e < cnt1) {
                int4 r4 = __ldg((const int4*)(g_csr + beg1 + e * 4));
                uint2 a0 = __ldg(((const uint2*)(g_th + (size_t)r4.x * H)) + lane);
                uint2 a1 = __ldg(((const uint2*)(g_th + (size_t)r4.y * H)) + lane);
                uint2 a2 = __ldg(((const uint2*)(g_th + (size_t)r4.z * H)) + lane);
                uint2 a3 = __ldg(((const uint2*)(g_th + (size_t)r4.w * H)) + lane);
                float2 f;
                f = __half22float2(*(__half2*)&a0.x); accB.x += f.x; accB.y += f.y;
                f = __half22float2(*(__half2*)&a0.y); accB.z += f.x; accB.w += f.y;
                f = __half22float2(*(__half2*)&a1.x); accB.x += f.x; accB.y += f.y;
                f = __half22float2(*(__half2*)&a1.y); accB.z += f.x; accB.w += f.y;
                f = __half22float2(*(__half2*)&a2.x); accB.x += f.x; accB.y += f.y;
                f = __half22float2(*(__half2*)&a2.y); accB.z += f.x; accB.w += f.y;
                f = __half22float2(*(__half2*)&a3.x); accB.x += f.x; accB.y += f.y;
                f = __half22float2(*(__half2*)&a3.y); accB.z += f.x; accB.w += f.y;
            }
        }

        accA.x *= dis0; accA.y *= dis0; accA.z *= dis0; accA.w *= dis0;
        ((float4*)(g_agg + (size_t)c0 * H))[lane] = accA;
        lsum.x += accA.x; lsum.y += accA.y; lsum.z += accA.z; lsum.w += accA.w;
        lsq.x += accA.x * accA.x; lsq.y += accA.y * accA.y;
        lsq.z += accA.z * accA.z; lsq.w += accA.w * accA.w;
        if (has1) {
            accB.x *= dis1; accB.y *= dis1; accB.z *= dis1; accB.w *= dis1;
            ((float4*)(g_agg + (size_t)c1 * H))[lane] = accB;
            lsum.x += accB.x; lsum.y += accB.y; lsum.z += accB.z; lsum.w += accB.w;
            lsq.x += accB.x * accB.x; lsq.y += accB.y * accB.y;
            lsq.z += accB.z * accB.z; lsq.w += accB.w * accB.w;
        }
    }

    __shared__ float ssum[H], ssq[H];
    if (threadIdx.x < H) { ssum[threadIdx.x] = 0.f; ssq[threadIdx.x] = 0.f; }
    __syncthreads();
    int f = lane * 4;
    atomicAdd(&ssum[f + 0], lsum.x);
    atomicAdd(&ssum[f + 1], lsum.y);
    atomicAdd(&ssum[f + 2], lsum.z);
    atomicAdd(&ssum[f + 3], lsum.w);
    atomicAdd(&ssq[f + 0], lsq.x);
    atomicAdd(&ssq[f + 1], lsq.y);
    atomicAdd(&ssq[f + 2], lsq.z);
    atomicAdd(&ssq[f + 3], lsq.w);
    __syncthreads();
    if (threadIdx.x < H) {
        double* ds = DUMMY ? g_dsumD : g_dsum;
        double* dq = DUMMY ? g_dsqD : g_dsq;
        atomicAdd(&ds[threadIdx.x], (double)ssum[threadIdx.x]);
        atomicAdd(&dq[threadIdx.x], (double)ssq[threadIdx.x]);
    }
}

// ---------------------------------------------------------------------------
// finalize BN params; zero stats (incl. probe sinks) for next layer
// ---------------------------------------------------------------------------
__global__ void finalize_kernel(const float* __restrict__ gamma,
                                const float* __restrict__ beta, int N) {
    int f = threadIdx.x;
    if (f >= H) return;
    double mu = g_dsum[f] / N;
    double var = g_dsq[f] / N - mu * mu;
    g_dsum[f] = 0.0;
    g_dsq[f] = 0.0;
    g_dsumD[f] = 0.0;
    g_dsqD[f] = 0.0;
    float inv = rsqrtf((float)var + 1e-5f);
    float s = gamma[f] * inv;
    g_scale[f] = s;
    g_shift[f] = beta[f] - (float)mu * s;
}

// ---------------------------------------------------------------------------
// pooling (fuses BN+SiLU of last layer; exploits sorted batch ids)
// ---------------------------------------------------------------------------
__global__ void pool_kernel(const void* batch, int N) {
    const float* A = g_agg;
    int f = threadIdx.x;  // blockDim = 128
    float sc = g_scale[f], sh = g_shift[f];
    int rowsPer = (N + gridDim.x - 1) / gridDim.x;
    int r0 = blockIdx.x * rowsPer;
    int r1 = min(N, r0 + rowsPer);
    int is64 = g_is64;
    int curG = -1;
    float acc = 0.f, cacc = 0.f;
    for (int r = r0; r < r1; r++) {
        int g = ldidx(batch, r, is64);
        if (g != curG) {
            if (curG >= 0) {
                atomicAdd(&g_pool[curG * H + f], acc);
                if (f == 0) atomicAdd(&g_cnt[curG], cacc);
            }
            curG = g;
            acc = 0.f;
            cacc = 0.f;
        }
        float v = fmaf(__ldg(&A[(size_t)r * H + f]), sc, sh);
        acc += silu_f(v);
        cacc += 1.f;
    }
    if (curG >= 0) {
        atomicAdd(&g_pool[curG * H + f], acc);
        if (f == 0) atomicAdd(&g_cnt[curG], cacc);
    }
}

// ---------------------------------------------------------------------------
// MLP head
// ---------------------------------------------------------------------------
__global__ void mlp_kernel(const float* __restrict__ fc1w,
                           const float* __restrict__ fc1b,
                           const float* __restrict__ fc2w,
                           const float* __restrict__ fc2b, float* __restrict__ out,
                           int G) {
    int g = blockIdx.x;
    if (g >= G) return;
    int t = threadIdx.x;  // 64 threads
    __shared__ float p[H];
    __shared__ float invc_s;
    __shared__ float warpsum[2];
    if (t == 0) invc_s = __fdividef(1.f, fmaxf(g_cnt[g], 1.f));
    __syncthreads();
    float invc = invc_s;
    p[t] = g_pool[g * H + t] * invc;
    p[t + 64] = g_pool[g * H + t + 64] * invc;
    __syncthreads();
    float acc = fc1b[t];
#pragma unroll
    for (int k = 0; k < H; k++) acc = fmaf(p[k], fc1w[k * 64 + t], acc);
    float z = silu_f(acc);
    float part = z * fc2w[t];
#pragma unroll
    for (int off = 16; off > 0; off >>= 1)
        part += __shfl_down_sync(0xffffffffu, part, off);
    if ((t & 31) == 0) warpsum[t >> 5] = part;
    __syncthreads();
    if (t == 0) {
        float sum = warpsum[0] + warpsum[1] + fc2b[0];
        out[g] = __fdividef(1.f, 1.f + __expf(-sum));
    }
}

// ---------------------------------------------------------------------------
// host
// ---------------------------------------------------------------------------
static inline int nblk(long long n, int t) { return (int)((n + t - 1) / t); }

extern "C" void kernel_launch(void* const* d_in, const int* in_sizes, int n_in,
                              void* d_out, int out_size) {
    int N = in_sizes[0];
    int E = in_sizes[1] / 2;
    int base = (in_sizes[3] == 1) ? 4 : 3;

    const float* x = (const float*)d_in[0];
    const void* ei = d_in[1];
    const void* batch = d_in[2];
    const float* W0 = (const float*)d_in[base + 0];
    const float* Ws = (const float*)d_in[base + 1];
    // biases (base+2) cancel exactly inside BatchNorm -> unused
    const float* gammas = (const float*)d_in[base + 3];
    const float* betas = (const float*)d_in[base + 4];
    const float* fc1w = (const float*)d_in[base + 5];
    const float* fc1b = (const float*)d_in[base + 6];
    const float* fc2w = (const float*)d_in[base + 7];
    const float* fc2b = (const float*)d_in[base + 8];
    float* out = (float*)d_out;
    int G = out_size;

    cudaFuncSetAttribute(gemm_kernel<0>, cudaFuncAttributeMaxDynamicSharedMemorySize,
                         GEMM_SMEM_BYTES);
    cudaFuncSetAttribute(gemm_kernel<1>, cudaFuncAttributeMaxDynamicSharedMemorySize,
                         GEMM_SMEM_BYTES);

    int GP = G * H;
    long long initSpan = (long long)N;
    if (GP > initSpan) initSpan = GP;
    int gB = nblk(N, 128);
    int gatherB = 1184;  // 8 blocks x 148 SMs

    // launches 1-3: prep
    init_kernel<<<nblk(initSpan, 256), 256>>>(ei, N, GP, G);        // 1
    indeg_count_kernel<<<nblk(E, 256), 256>>>(ei, E);               // 2
    wprep_kernel<<<nblk(3 * H * H, 256), 256>>>(Ws);                // 3
    // launch 4: DUMMY gather probe over N/4 nodes (ncu captures the 4th
    // launch). Reads prior-replay CSR/messages (deterministic; zeros on
    // first call), writes g_agg subset fully overwritten by the real
    // layer-1 gather; stats go to sink buffers. d_out unaffected.
    gather_kernel<1><<<gatherB, 256>>>(N / 4);                      // 4
    assign_kernel<<<nblk(N, 256), 256>>>(x, N);                     // 5
    fill_kernel<<<nblk(E, 256), 256>>>(ei, E);                      // 6

    // layer 0 (rank-1 scalar path)
    layer0_kernel<<<nblk(N, 256), 256>>>(N);
    coef0_kernel<<<1, 128>>>(W0, gammas, betas, N);

    // layer 1
    gemm_kernel<0><<<gB, 512, GEMM_SMEM_BYTES>>>(0, N);
    gather_kernel<0><<<gatherB, 256>>>(N);
    finalize_kernel<<<1, 128>>>(gammas + H, betas + H, N);

    // layer 2
    gemm_kernel<1><<<gB, 512, GEMM_SMEM_BYTES>>>(1, N);
    gather_kernel<0><<<gatherB, 256>>>(N);
    finalize_kernel<<<1, 128>>>(gammas + 2 * H, betas + 2 * H, N);

    // layer 3
    gemm_kernel<1><<<gB, 512, GEMM_SMEM_BYTES>>>(2, N);
    gather_kernel<0><<<gatherB, 256>>>(N);
    finalize_kernel<<<1, 128>>>(gammas + 3 * H, betas + 3 * H, N);

    // pooling + head
    pool_kernel<<<1024, 128>>>(batch, N);
    mlp_kernel<<<G, 64>>>(fc1w, fc1b, fc2w, fc2b, out, G);
}

// round 14
// speedup vs baseline: 1.1357x; 1.1357x over previous
#include <cuda_runtime.h>
#include <cuda_fp16.h>
#include <math.h>

// ============================================================================
// SurfaceCodeGNN: 4-layer GCN + BN/SiLU + mean-pool + MLP head
// N=100000, E=600000, H=128, G=256
//
// Round 14 (consolidation, resubmitted with one tweak after 2x infra
// failure): R8's gather/layer0/assign (unpadded CSR, scalar index loads)
// + R10's 512-thread tensor-core GEMM (probe-verified faster) + probe
// removed + pool now uses single-MUFU tanh-based SiLU.
// ============================================================================

#define H 128
#define MAXN 100352
#define MAXE 1200000
#define MAXG 1024

__device__ __half g_th[(size_t)MAXN * H];    // pre-scaled messages dis[r]*t[r]
__device__ float  g_agg[(size_t)MAXN * H];   // gather output (pre-BN)
__device__ __half g_wt[3 * H * H];           // W transposed [layer][n][k] fp16
__device__ float  g_s[MAXN];
__device__ float  g_sx[MAXN];                // dis[i]*x[i]
__device__ float  g_dis[MAXN];
__device__ int    g_indeg[MAXN];
__device__ int    g_rowptr[MAXN];
__device__ int    g_cursor[MAXN];
__device__ int    g_csr[MAXE];
__device__ int    g_ctr;
__device__ double g_dsum[H], g_dsq[H];
__device__ double g_sstats[2];
__device__ float  g_scale[H], g_shift[H];
__device__ float  g_C0[H], g_B0[H];
__device__ float  g_pool[MAXG * H];
__device__ float  g_cnt[MAXG];
__device__ int    g_is64;

static __device__ __forceinline__ float silu_f(float x) {
    float e = __expf(-x);
    return __fdividef(x, 1.0f + e);
}

// silu via single-MUFU hw tanh: x*sigmoid(x) = 0.5x + 0.5x*tanh(x/2)
static __device__ __forceinline__ float silu_t(float x) {
    float t;
    asm("tanh.approx.f32 %0, %1;" : "=f"(t) : "f"(0.5f * x));
    return fmaf(0.5f * x, t, 0.5f * x);
}

static __device__ __forceinline__ int ldidx(const void* p, long long i, int is64) {
    return ((const int*)p)[is64 ? 2 * i : i];
}

// ---------------------------------------------------------------------------
// init: zero indeg/pool/cnt/counters; detect index dtype
// ---------------------------------------------------------------------------
__global__ void init_kernel(const void* ei, int N, int GP, int G) {
    int i = blockIdx.x * blockDim.x + threadIdx.x;
    if (i < N) g_indeg[i] = 0;
    if (i < GP) g_pool[i] = 0.f;
    if (i < G) g_cnt[i] = 0.f;
    if (i == 0) {
        g_ctr = 0;
        g_sstats[0] = 0.0;
        g_sstats[1] = 0.0;
    }
    if (blockIdx.x == 0 && threadIdx.x < 32) {
        int any = 0;
        const int* p = (const int*)ei;
        for (int k = threadIdx.x; k < 64; k += 32)
            if (p[2 * k + 1] != 0) any = 1;
        any = __any_sync(0xffffffffu, any);
        if (threadIdx.x == 0) g_is64 = any ? 0 : 1;
    }
}

__global__ void indeg_count_kernel(const void* ei, int E) {
    int e = blockIdx.x * blockDim.x + threadIdx.x;
    if (e >= E) return;
    int is64 = g_is64;
    int c = ldidx(ei, (long long)E + e, is64);
    atomicAdd(&g_indeg[c], 1);
}

// ---------------------------------------------------------------------------
// wprep: transpose/convert all 3 GCN weights to fp16 n-major (once)
// ---------------------------------------------------------------------------
__global__ void wprep_kernel(const float* __restrict__ Ws) {
    int i = blockIdx.x * blockDim.x + threadIdx.x;
    if (i >= 3 * H * H) return;
    int layer = i >> 14;
    int rem = i & 16383;
    int k = rem >> 7, n = rem & 127;
    g_wt[layer * H * H + n * H + k] = __float2half_rn(Ws[i]);
}

// ---------------------------------------------------------------------------
// assign: dis, sx = dis*x, rowptr via warp-aggregated atomic (unpadded)
// ---------------------------------------------------------------------------
__global__ void assign_kernel(const float* __restrict__ x, int N) {
    int i = blockIdx.x * blockDim.x + threadIdx.x;
    int lane = threadIdx.x & 31;
    int deg = (i < N) ? g_indeg[i] : 0;
    int v = deg;
#pragma unroll
    for (int off = 1; off < 32; off <<= 1) {
        int t = __shfl_up_sync(0xffffffffu, v, off);
        if (lane >= off) v += t;
    }
    int warpTot = __shfl_sync(0xffffffffu, v, 31);
    int base = 0;
    if (lane == 31) base = atomicAdd(&g_ctr, warpTot);
    base = __shfl_sync(0xffffffffu, base, 31);
    if (i < N) {
        int rp = base + v - deg;
        g_rowptr[i] = rp;
        g_cursor[i] = rp;
        float dis = rsqrtf((float)(deg + 1));  // +1 self loop
        g_dis[i] = dis;
        g_sx[i] = dis * x[i];
    }
}

__global__ void fill_kernel(const void* ei, int E) {
    int e = blockIdx.x * blockDim.x + threadIdx.x;
    if (e >= E) return;
    int is64 = g_is64;
    int r = ldidx(ei, e, is64);
    int c = ldidx(ei, (long long)E + e, is64);
    int p = atomicAdd(&g_cursor[c], 1);
    g_csr[p] = r;
}

// ---------------------------------------------------------------------------
// layer 0: s[c] = dis[c]*(sx[c] + sum_e sx[r]), + stats
// ---------------------------------------------------------------------------
__global__ void layer0_kernel(int N) {
    int i = blockIdx.x * blockDim.x + threadIdx.x;
    float sum = 0.f, sq = 0.f;
    if (i < N) {
        int beg = g_rowptr[i], cnt = g_indeg[i];
        float acc = g_sx[i];
        for (int e = beg; e < beg + cnt; e++) {
            int r = __ldg(&g_csr[e]);
            acc += __ldg(&g_sx[r]);
        }
        acc *= g_dis[i];
        g_s[i] = acc;
        sum = acc;
        sq = acc * acc;
    }
    __shared__ float sa[256], sb[256];
    sa[threadIdx.x] = sum;
    sb[threadIdx.x] = sq;
    __syncthreads();
    for (int off = 128; off > 0; off >>= 1) {
        if (threadIdx.x < off) {
            sa[threadIdx.x] += sa[threadIdx.x + off];
            sb[threadIdx.x] += sb[threadIdx.x + off];
        }
        __syncthreads();
    }
    if (threadIdx.x == 0) {
        atomicAdd(&g_sstats[0], (double)sa[0]);
        atomicAdd(&g_sstats[1], (double)sb[0]);
    }
}

__global__ void coef0_kernel(const float* __restrict__ W0,
                             const float* __restrict__ gamma0,
                             const float* __restrict__ beta0, int N) {
    int t = threadIdx.x;
    if (t >= H) return;
    g_dsum[t] = 0.0;
    g_dsq[t] = 0.0;
    double mu = g_sstats[0] / N;
    double var = g_sstats[1] / N - mu * mu;
    float w = W0[t];
    float inv = rsqrtf((float)var * w * w + 1e-5f);
    float c = w * inv * gamma0[t];
    g_C0[t] = c;
    g_B0[t] = beta0[t] - (float)mu * c;
}

// ---------------------------------------------------------------------------
// Tensor-core GEMM: th = half( dis[n] * (silu_bn(A) @ W) )
// 512 threads, 16 warps; warp w -> rows [(w>>1)*16,+16), cols [(w&1)*64,+64).
// mma.sync.m16n8k16 + ldmatrix.x4; Wt from pre-transposed g_wt (uint4 copy).
// ---------------------------------------------------------------------------
#define ASTRIDE 136  // halfs per padded row (272B -> ldmatrix conflict-free)
#define GEMM_SMEM_BYTES (34816 * 2 + 1024)

static __device__ __forceinline__ void mma16816(float& c0, float& c1, float& c2,
                                                float& c3, unsigned a0, unsigned a1,
                                                unsigned a2, unsigned a3,
                                                unsigned b0, unsigned b1) {
    asm volatile(
        "mma.sync.aligned.m16n8k16.row.col.f32.f16.f16.f32 "
        "{%0,%1,%2,%3}, {%4,%5,%6,%7}, {%8,%9}, {%0,%1,%2,%3};"
        : "+f"(c0), "+f"(c1), "+f"(c2), "+f"(c3)
        : "r"(a0), "r"(a1), "r"(a2), "r"(a3), "r"(b0), "r"(b1));
}

static __device__ __forceinline__ void ldsm4(unsigned& r0, unsigned& r1,
                                             unsigned& r2, unsigned& r3,
                                             unsigned addr) {
    asm volatile(
        "ldmatrix.sync.aligned.m8n8.x4.shared.b16 {%0,%1,%2,%3}, [%4];"
        : "=r"(r0), "=r"(r1), "=r"(r2), "=r"(r3)
        : "r"(addr));
}

template <int MODE>
__global__ void __launch_bounds__(512, 2)
gemm_kernel(int layer, int N) {
    extern __shared__ char smraw[];
    __half* As = (__half*)smraw;                  // [128][ASTRIDE]
    __half* Wt = (__half*)(smraw + 34816);        // [128][ASTRIDE] (n-major)
    float* scs = (float*)(smraw + 69632);         // 128
    float* shs = scs + 128;                       // 128

    const float* SRC = (MODE == 0) ? g_s : g_agg;
    const float* sc = (MODE == 0) ? g_C0 : g_scale;
    const float* sh = (MODE == 0) ? g_B0 : g_shift;

    int tid = threadIdx.x;
    if (tid < H) { scs[tid] = sc[tid]; shs[tid] = sh[tid]; }
    __syncthreads();

    int rowBase = blockIdx.x * 128;

    // stage Wt: coalesced conflict-free copy of pre-transposed weights
    {
        const uint4* wsrc4 = (const uint4*)(g_wt + layer * H * H);
        uint4* wdst4 = (uint4*)Wt;
#pragma unroll
        for (int i = tid; i < 2048; i += 512) {
            int n = i >> 4, cc = i & 15;
            wdst4[n * 17 + cc] = wsrc4[i];  // 17 uint4 per padded row
        }
    }

    // stage A (BN+SiLU fused) in fp16
    for (int i = tid; i < 4096; i += 512) {
        int r = i >> 5, kq = (i & 31) * 4;
        int gr = rowBase + r;
        float4 pre;
        if (gr < N) {
            if (MODE == 0) {
                float xin = g_s[gr];
                pre.x = fmaf(xin, scs[kq + 0], shs[kq + 0]);
                pre.y = fmaf(xin, scs[kq + 1], shs[kq + 1]);
                pre.z = fmaf(xin, scs[kq + 2], shs[kq + 2]);
                pre.w = fmaf(xin, scs[kq + 3], shs[kq + 3]);
            } else {
                float4 xin = __ldg((const float4*)(SRC + (size_t)gr * H + kq));
                pre.x = fmaf(xin.x, scs[kq + 0], shs[kq + 0]);
                pre.y = fmaf(xin.y, scs[kq + 1], shs[kq + 1]);
                pre.z = fmaf(xin.z, scs[kq + 2], shs[kq + 2]);
                pre.w = fmaf(xin.w, scs[kq + 3], shs[kq + 3]);
            }
            pre.x = silu_t(pre.x);
            pre.y = silu_t(pre.y);
            pre.z = silu_t(pre.z);
            pre.w = silu_t(pre.w);
        } else {
            pre = make_float4(0.f, 0.f, 0.f, 0.f);
        }
        __half2* dst = (__half2*)(As + r * ASTRIDE + kq);
        dst[0] = __floats2half2_rn(pre.x, pre.y);
        dst[1] = __floats2half2_rn(pre.z, pre.w);
    }
    __syncthreads();

    int warp = tid >> 5, lane = tid & 31;
    int g = lane >> 2, tig = lane & 3;
    int rbase = (warp >> 1) * 16;
    int colbase = (warp & 1) * 64;

    unsigned asu = (unsigned)__cvta_generic_to_shared(As);
    unsigned wtu = (unsigned)__cvta_generic_to_shared(Wt);
    int rowA = rbase + ((lane >> 3) & 1) * 8 + (lane & 7);
    int colA = (lane >> 4) * 8;
    unsigned aAddr = asu + (unsigned)((rowA * ASTRIDE + colA) * 2);
    int nrowB = colbase + (lane >> 4) * 8 + (lane & 7);
    int colB = ((lane >> 3) & 1) * 8;
    unsigned bAddr = wtu + (unsigned)((nrowB * ASTRIDE + colB) * 2);

    float c[8][4];
#pragma unroll
    for (int j = 0; j < 8; j++)
#pragma unroll
        for (int q = 0; q < 4; q++) c[j][q] = 0.f;

#pragma unroll
    for (int k0 = 0; k0 < 128; k0 += 16) {
        unsigned a0, a1, a2, a3;
        ldsm4(a0, a1, a2, a3, aAddr + k0 * 2);
#pragma unroll
        for (int jj = 0; jj < 4; jj++) {
            unsigned b0, b1, b2, b3;
            ldsm4(b0, b1, b2, b3,
                  bAddr + (unsigned)(jj * (16 * ASTRIDE * 2) + k0 * 2));
            mma16816(c[2 * jj][0], c[2 * jj][1], c[2 * jj][2], c[2 * jj][3],
                     a0, a1, a2, a3, b0, b1);
            mma16816(c[2 * jj + 1][0], c[2 * jj + 1][1], c[2 * jj + 1][2],
                     c[2 * jj + 1][3], a0, a1, a2, a3, b2, b3);
        }
    }

    // epilogue: th[row] = half(dis[row] * out), 64 cols per warp
    int r0 = rowBase + rbase + g;
    int r1 = r0 + 8;
    float d0 = (r0 < N) ? __ldg(&g_dis[r0]) : 0.f;
    float d1 = (r1 < N) ? __ldg(&g_dis[r1]) : 0.f;
    __half* out0 = g_th + (size_t)r0 * H + colbase + 2 * tig;
    __half* out1 = g_th + (size_t)r1 * H + colbase + 2 * tig;
#pragma unroll
    for (int j = 0; j < 8; j++) {
        if (r0 < N)
            *(__half2*)(out0 + j * 8) = __floats2half2_rn(c[j][0] * d0, c[j][1] * d0);
        if (r1 < N)
            *(__half2*)(out1 + j * 8) = __floats2half2_rn(c[j][2] * d1, c[j][3] * d1);
    }
}

// ---------------------------------------------------------------------------
// gather: agg[c] = dis[c]*(tS[c] + sum_e tS[r]);  BN stats fused.
// One node per warp, scalar 4x index loads + remainder (R8 form — fastest
// measured variant; no dummy-row loads, 40 regs -> high occupancy).
// ---------------------------------------------------------------------------
__global__ void __launch_bounds__(256) gather_kernel(int N) {
    int lane = threadIdx.x & 31;
    int gw = blockIdx.x * 8 + (threadIdx.x >> 5);
    int nw = gridDim.x * 8;

    float4 lsum = make_float4(0.f, 0.f, 0.f, 0.f);
    float4 lsq = make_float4(0.f, 0.f, 0.f, 0.f);

    for (int c = gw; c < N; c += nw) {
        int beg = __ldg(&g_rowptr[c]);
        int end = beg + __ldg(&g_indeg[c]);
        float disc = __ldg(&g_dis[c]);
        uint2 sraw = __ldg(((const uint2*)(g_th + (size_t)c * H)) + lane);
        float2 s0 = __half22float2(*(__half2*)&sraw.x);
        float2 s1 = __half22float2(*(__half2*)&sraw.y);
        float4 acc = make_float4(s0.x, s0.y, s1.x, s1.y);
        int e = beg;
        for (; e + 4 <= end; e += 4) {
            int r0 = __ldg(&g_csr[e + 0]);
            int r1 = __ldg(&g_csr[e + 1]);
            int r2 = __ldg(&g_csr[e + 2]);
            int r3 = __ldg(&g_csr[e + 3]);
            uint2 a0 = __ldg(((const uint2*)(g_th + (size_t)r0 * H)) + lane);
            uint2 a1 = __ldg(((const uint2*)(g_th + (size_t)r1 * H)) + lane);
            uint2 a2 = __ldg(((const uint2*)(g_th + (size_t)r2 * H)) + lane);
            uint2 a3 = __ldg(((const uint2*)(g_th + (size_t)r3 * H)) + lane);
            float2 f;
            f = __half22float2(*(__half2*)&a0.x); acc.x += f.x; acc.y += f.y;
            f = __half22float2(*(__half2*)&a0.y); acc.z += f.x; acc.w += f.y;
            f = __half22float2(*(__half2*)&a1.x); acc.x += f.x; acc.y += f.y;
            f = __half22float2(*(__half2*)&a1.y); acc.z += f.x; acc.w += f.y;
            f = __half22float2(*(__half2*)&a2.x); acc.x += f.x; acc.y += f.y;
            f = __half22float2(*(__half2*)&a2.y); acc.z += f.x; acc.w += f.y;
            f = __half22float2(*(__half2*)&a3.x); acc.x += f.x; acc.y += f.y;
            f = __half22float2(*(__half2*)&a3.y); acc.z += f.x; acc.w += f.y;
        }
        for (; e < end; e++) {
            int r0 = __ldg(&g_csr[e]);
            uint2 a0 = __ldg(((const uint2*)(g_th + (size_t)r0 * H)) + lane);
            float2 f;
            f = __half22float2(*(__half2*)&a0.x); acc.x += f.x; acc.y += f.y;
            f = __half22float2(*(__half2*)&a0.y); acc.z += f.x; acc.w += f.y;
        }
        acc.x *= disc; acc.y *= disc; acc.z *= disc; acc.w *= disc;
        ((float4*)(g_agg + (size_t)c * H))[lane] = acc;
        lsum.x += acc.x; lsum.y += acc.y; lsum.z += acc.z; lsum.w += acc.w;
        lsq.x += acc.x * acc.x; lsq.y += acc.y * acc.y;
        lsq.z += acc.z * acc.z; lsq.w += acc.w * acc.w;
    }

    __shared__ float ssum[H], ssq[H];
    if (threadIdx.x < H) { ssum[threadIdx.x] = 0.f; ssq[threadIdx.x] = 0.f; }
    __syncthreads();
    int f = lane * 4;
    atomicAdd(&ssum[f + 0], lsum.x);
    atomicAdd(&ssum[f + 1], lsum.y);
    atomicAdd(&ssum[f + 2], lsum.z);
    atomicAdd(&ssum[f + 3], lsum.w);
    atomicAdd(&ssq[f + 0], lsq.x);
    atomicAdd(&ssq[f + 1], lsq.y);
    atomicAdd(&ssq[f + 2], lsq.z);
    atomicAdd(&ssq[f + 3], lsq.w);
    __syncthreads();
    if (threadIdx.x < H) {
        atomicAdd(&g_dsum[threadIdx.x], (double)ssum[threadIdx.x]);
        atomicAdd(&g_dsq[threadIdx.x], (double)ssq[threadIdx.x]);
    }
}

// ---------------------------------------------------------------------------
// finalize BN params; zero stats for next layer
// ---------------------------------------------------------------------------
__global__ void finalize_kernel(const float* __restrict__ gamma,
                                const float* __restrict__ beta, int N) {
    int f = threadIdx.x;
    if (f >= H) return;
    double mu = g_dsum[f] / N;
    double var = g_dsq[f] / N - mu * mu;
    g_dsum[f] = 0.0;
    g_dsq[f] = 0.0;
    float inv = rsqrtf((float)var + 1e-5f);
    float s = gamma[f] * inv;
    g_scale[f] = s;
    g_shift[f] = beta[f] - (float)mu * s;
}

// ---------------------------------------------------------------------------
// pooling (fuses BN+SiLU of last layer; exploits sorted batch ids)
// ---------------------------------------------------------------------------
__global__ void pool_kernel(const void* batch, int N) {
    const float* A = g_agg;
    int f = threadIdx.x;  // blockDim = 128
    float sc = g_scale[f], sh = g_shift[f];
    int rowsPer = (N + gridDim.x - 1) / gridDim.x;
    int r0 = blockIdx.x * rowsPer;
    int r1 = min(N, r0 + rowsPer);
    int is64 = g_is64;
    int curG = -1;
    float acc = 0.f, cacc = 0.f;
    for (int r = r0; r < r1; r++) {
        int g = ldidx(batch, r, is64);
        if (g != curG) {
            if (curG >= 0) {
                atomicAdd(&g_pool[curG * H + f], acc);
                if (f == 0) atomicAdd(&g_cnt[curG], cacc);
            }
            curG = g;
            acc = 0.f;
            cacc = 0.f;
        }
        float v = fmaf(__ldg(&A[(size_t)r * H + f]), sc, sh);
        acc += silu_t(v);
        cacc += 1.f;
    }
    if (curG >= 0) {
        atomicAdd(&g_pool[curG * H + f], acc);
        if (f == 0) atomicAdd(&g_cnt[curG], cacc);
    }
}

// ---------------------------------------------------------------------------
// MLP head
// ---------------------------------------------------------------------------
__global__ void mlp_kernel(const float* __restrict__ fc1w,
                           const float* __restrict__ fc1b,
                           const float* __restrict__ fc2w,
                           const float* __restrict__ fc2b, float* __restrict__ out,
                           int G) {
    int g = blockIdx.x;
    if (g >= G) return;
    int t = threadIdx.x;  // 64 threads
    __shared__ float p[H];
    __shared__ float invc_s;
    __shared__ float warpsum[2];
    if (t == 0) invc_s = __fdividef(1.f, fmaxf(g_cnt[g], 1.f));
    __syncthreads();
    float invc = invc_s;
    p[t] = g_pool[g * H + t] * invc;
    p[t + 64] = g_pool[g * H + t + 64] * invc;
    __syncthreads();
    float acc = fc1b[t];
#pragma unroll
    for (int k = 0; k < H; k++) acc = fmaf(p[k], fc1w[k * 64 + t], acc);
    float z = silu_f(acc);
    float part = z * fc2w[t];
#pragma unroll
    for (int off = 16; off > 0; off >>= 1)
        part += __shfl_down_sync(0xffffffffu, part, off);
    if ((t & 31) == 0) warpsum[t >> 5] = part;
    __syncthreads();
    if (t == 0) {
        float sum = warpsum[0] + warpsum[1] + fc2b[0];
        out[g] = __fdividef(1.f, 1.f + __expf(-sum));
    }
}

// ---------------------------------------------------------------------------
// host
// ---------------------------------------------------------------------------
static inline int nblk(long long n, int t) { return (int)((n + t - 1) / t); }

extern "C" void kernel_launch(void* const* d_in, const int* in_sizes, int n_in,
                              void* d_out, int out_size) {
    int N = in_sizes[0];
    int E = in_sizes[1] / 2;
    int base = (in_sizes[3] == 1) ? 4 : 3;

    const float* x = (const float*)d_in[0];
    const void* ei = d_in[1];
    const void* batch = d_in[2];
    const float* W0 = (const float*)d_in[base + 0];
    const float* Ws = (const float*)d_in[base + 1];
    // biases (base+2) cancel exactly inside BatchNorm -> unused
    const float* gammas = (const float*)d_in[base + 3];
    const float* betas = (const float*)d_in[base + 4];
    const float* fc1w = (const float*)d_in[base + 5];
    const float* fc1b = (const float*)d_in[base + 6];
    const float* fc2w = (const float*)d_in[base + 7];
    const float* fc2b = (const float*)d_in[base + 8];
    float* out = (float*)d_out;
    int G = out_size;

    cudaFuncSetAttribute(gemm_kernel<0>, cudaFuncAttributeMaxDynamicSharedMemorySize,
                         GEMM_SMEM_BYTES);
    cudaFuncSetAttribute(gemm_kernel<1>, cudaFuncAttributeMaxDynamicSharedMemorySize,
                         GEMM_SMEM_BYTES);

    int GP = G * H;
    long long initSpan = (long long)N;
    if (GP > initSpan) initSpan = GP;
    int gB = nblk(N, 128);
    int gatherB = 1184;  // 8 blocks x 148 SMs

    // prep
    init_kernel<<<nblk(initSpan, 256), 256>>>(ei, N, GP, G);
    indeg_count_kernel<<<nblk(E, 256), 256>>>(ei, E);
    wprep_kernel<<<nblk(3 * H * H, 256), 256>>>(Ws);
    assign_kernel<<<nblk(N, 256), 256>>>(x, N);
    fill_kernel<<<nblk(E, 256), 256>>>(ei, E);

    // layer 0 (rank-1 scalar path)
    layer0_kernel<<<nblk(N, 256), 256>>>(N);
    coef0_kernel<<<1, 128>>>(W0, gammas, betas, N);

    // layer 1
    gemm_kernel<0><<<gB, 512, GEMM_SMEM_BYTES>>>(0, N);
    gather_kernel<<<gatherB, 256>>>(N);
    finalize_kernel<<<1, 128>>>(gammas + H, betas + H, N);

    // layer 2
    gemm_kernel<1><<<gB, 512, GEMM_SMEM_BYTES>>>(1, N);
    gather_kernel<<<gatherB, 256>>>(N);
    finalize_kernel<<<1, 128>>>(gammas + 2 * H, betas + 2 * H, N);

    // layer 3
    gemm_kernel<1><<<gB, 512, GEMM_SMEM_BYTES>>>(2, N);
    gather_kernel<<<gatherB, 256>>>(N);
    finalize_kernel<<<1, 128>>>(gammas + 3 * H, betas + 3 * H, N);

    // pooling + head
    pool_kernel<<<1024, 128>>>(batch, N);
    mlp_kernel<<<G, 64>>>(fc1w, fc1b, fc2w, fc2b, out, G);
}

// round 16
// speedup vs baseline: 1.1541x; 1.0162x over previous
#include <cuda_runtime.h>
#include <cuda_fp16.h>
#include <math.h>

// ============================================================================
// SurfaceCodeGNN: 4-layer GCN + BN/SiLU + mean-pool + MLP head
// N=100000, E=600000, H=128, G=256
//
// Round 16 (= Round 15 resubmitted after transient infra failure):
// gather accumulates in fp16 via HADD2 (2 instr/row vs 6-8 for unpack+FADD;
// kernel is ~44% issue-bound), wprep folded into init_kernel, mlp uses
// tanh SiLU. GEMM/pool/layer0 as R14 (best = 317.4us).
// ============================================================================

#define H 128
#define MAXN 100352
#define MAXE 1200000
#define MAXG 1024

__device__ __half g_th[(size_t)MAXN * H];    // pre-scaled messages dis[r]*t[r]
__device__ float  g_agg[(size_t)MAXN * H];   // gather output (pre-BN)
__device__ __half g_wt[3 * H * H];           // W transposed [layer][n][k] fp16
__device__ float  g_s[MAXN];
__device__ float  g_sx[MAXN];                // dis[i]*x[i]
__device__ float  g_dis[MAXN];
__device__ int    g_indeg[MAXN];
__device__ int    g_rowptr[MAXN];
__device__ int    g_cursor[MAXN];
__device__ int    g_csr[MAXE];
__device__ int    g_ctr;
__device__ double g_dsum[H], g_dsq[H];
__device__ double g_sstats[2];
__device__ float  g_scale[H], g_shift[H];
__device__ float  g_C0[H], g_B0[H];
__device__ float  g_pool[MAXG * H];
__device__ float  g_cnt[MAXG];
__device__ int    g_is64;

static __device__ __forceinline__ float silu_f(float x) {
    float e = __expf(-x);
    return __fdividef(x, 1.0f + e);
}

// silu via single-MUFU hw tanh: x*sigmoid(x) = 0.5x + 0.5x*tanh(x/2)
static __device__ __forceinline__ float silu_t(float x) {
    float t;
    asm("tanh.approx.f32 %0, %1;" : "=f"(t) : "f"(0.5f * x));
    return fmaf(0.5f * x, t, 0.5f * x);
}

static __device__ __forceinline__ int ldidx(const void* p, long long i, int is64) {
    return ((const int*)p)[is64 ? 2 * i : i];
}

// ---------------------------------------------------------------------------
// init: zero indeg/pool/cnt/counters; transpose W to fp16 n-major; detect
// index dtype. (3*H*H = 49152 < N so the i-span covers the transpose.)
// ---------------------------------------------------------------------------
__global__ void init_kernel(const void* ei, const float* __restrict__ Ws,
                            int N, int GP, int G) {
    int i = blockIdx.x * blockDim.x + threadIdx.x;
    if (i < N) g_indeg[i] = 0;
    if (i < GP) g_pool[i] = 0.f;
    if (i < G) g_cnt[i] = 0.f;
    if (i < 3 * H * H) {
        int layer = i >> 14;
        int rem = i & 16383;
        int k = rem >> 7, n = rem & 127;
        g_wt[layer * H * H + n * H + k] = __float2half_rn(Ws[i]);
    }
    if (i == 0) {
        g_ctr = 0;
        g_sstats[0] = 0.0;
        g_sstats[1] = 0.0;
    }
    if (blockIdx.x == 0 && threadIdx.x < 32) {
        int any = 0;
        const int* p = (const int*)ei;
        for (int k = threadIdx.x; k < 64; k += 32)
            if (p[2 * k + 1] != 0) any = 1;
        any = __any_sync(0xffffffffu, any);
        if (threadIdx.x == 0) g_is64 = any ? 0 : 1;
    }
}

__global__ void indeg_count_kernel(const void* ei, int E) {
    int e = blockIdx.x * blockDim.x + threadIdx.x;
    if (e >= E) return;
    int is64 = g_is64;
    int c = ldidx(ei, (long long)E + e, is64);
    atomicAdd(&g_indeg[c], 1);
}

// ---------------------------------------------------------------------------
// assign: dis, sx = dis*x, rowptr via warp-aggregated atomic (unpadded)
// ---------------------------------------------------------------------------
__global__ void assign_kernel(const float* __restrict__ x, int N) {
    int i = blockIdx.x * blockDim.x + threadIdx.x;
    int lane = threadIdx.x & 31;
    int deg = (i < N) ? g_indeg[i] : 0;
    int v = deg;
#pragma unroll
    for (int off = 1; off < 32; off <<= 1) {
        int t = __shfl_up_sync(0xffffffffu, v, off);
        if (lane >= off) v += t;
    }
    int warpTot = __shfl_sync(0xffffffffu, v, 31);
    int base = 0;
    if (lane == 31) base = atomicAdd(&g_ctr, warpTot);
    base = __shfl_sync(0xffffffffu, base, 31);
    if (i < N) {
        int rp = base + v - deg;
        g_rowptr[i] = rp;
        g_cursor[i] = rp;
        float dis = rsqrtf((float)(deg + 1));  // +1 self loop
        g_dis[i] = dis;
        g_sx[i] = dis * x[i];
    }
}

__global__ void fill_kernel(const void* ei, int E) {
    int e = blockIdx.x * blockDim.x + threadIdx.x;
    if (e >= E) return;
    int is64 = g_is64;
    int r = ldidx(ei, e, is64);
    int c = ldidx(ei, (long long)E + e, is64);
    int p = atomicAdd(&g_cursor[c], 1);
    g_csr[p] = r;
}

// ---------------------------------------------------------------------------
// layer 0: s[c] = dis[c]*(sx[c] + sum_e sx[r]), + stats
// ---------------------------------------------------------------------------
__global__ void layer0_kernel(int N) {
    int i = blockIdx.x * blockDim.x + threadIdx.x;
    float sum = 0.f, sq = 0.f;
    if (i < N) {
        int beg = g_rowptr[i], cnt = g_indeg[i];
        float acc = g_sx[i];
        for (int e = beg; e < beg + cnt; e++) {
            int r = __ldg(&g_csr[e]);
            acc += __ldg(&g_sx[r]);
        }
        acc *= g_dis[i];
        g_s[i] = acc;
        sum = acc;
        sq = acc * acc;
    }
    __shared__ float sa[256], sb[256];
    sa[threadIdx.x] = sum;
    sb[threadIdx.x] = sq;
    __syncthreads();
    for (int off = 128; off > 0; off >>= 1) {
        if (threadIdx.x < off) {
            sa[threadIdx.x] += sa[threadIdx.x + off];
            sb[threadIdx.x] += sb[threadIdx.x + off];
        }
        __syncthreads();
    }
    if (threadIdx.x == 0) {
        atomicAdd(&g_sstats[0], (double)sa[0]);
        atomicAdd(&g_sstats[1], (double)sb[0]);
    }
}

__global__ void coef0_kernel(const float* __restrict__ W0,
                             const float* __restrict__ gamma0,
                             const float* __restrict__ beta0, int N) {
    int t = threadIdx.x;
    if (t >= H) return;
    g_dsum[t] = 0.0;
    g_dsq[t] = 0.0;
    double mu = g_sstats[0] / N;
    double var = g_sstats[1] / N - mu * mu;
    float w = W0[t];
    float inv = rsqrtf((float)var * w * w + 1e-5f);
    float c = w * inv * gamma0[t];
    g_C0[t] = c;
    g_B0[t] = beta0[t] - (float)mu * c;
}

// ---------------------------------------------------------------------------
// Tensor-core GEMM: th = half( dis[n] * (silu_bn(A) @ W) )
// 512 threads, 16 warps; warp w -> rows [(w>>1)*16,+16), cols [(w&1)*64,+64).
// mma.sync.m16n8k16 + ldmatrix.x4; Wt from pre-transposed g_wt (uint4 copy).
// ---------------------------------------------------------------------------
#define ASTRIDE 136  // halfs per padded row (272B -> ldmatrix conflict-free)
#define GEMM_SMEM_BYTES (34816 * 2 + 1024)

static __device__ __forceinline__ void mma16816(float& c0, float& c1, float& c2,
                                                float& c3, unsigned a0, unsigned a1,
                                                unsigned a2, unsigned a3,
                                                unsigned b0, unsigned b1) {
    asm volatile(
        "mma.sync.aligned.m16n8k16.row.col.f32.f16.f16.f32 "
        "{%0,%1,%2,%3}, {%4,%5,%6,%7}, {%8,%9}, {%0,%1,%2,%3};"
        : "+f"(c0), "+f"(c1), "+f"(c2), "+f"(c3)
        : "r"(a0), "r"(a1), "r"(a2), "r"(a3), "r"(b0), "r"(b1));
}

static __device__ __forceinline__ void ldsm4(unsigned& r0, unsigned& r1,
                                             unsigned& r2, unsigned& r3,
                                             unsigned addr) {
    asm volatile(
        "ldmatrix.sync.aligned.m8n8.x4.shared.b16 {%0,%1,%2,%3}, [%4];"
        : "=r"(r0), "=r"(r1), "=r"(r2), "=r"(r3)
        : "r"(addr));
}

template <int MODE>
__global__ void __launch_bounds__(512, 2)
gemm_kernel(int layer, int N) {
    extern __shared__ char smraw[];
    __half* As = (__half*)smraw;                  // [128][ASTRIDE]
    __half* Wt = (__half*)(smraw + 34816);        // [128][ASTRIDE] (n-major)
    float* scs = (float*)(smraw + 69632);         // 128
    float* shs = scs + 128;                       // 128

    const float* SRC = (MODE == 0) ? g_s : g_agg;
    const float* sc = (MODE == 0) ? g_C0 : g_scale;
    const float* sh = (MODE == 0) ? g_B0 : g_shift;

    int tid = threadIdx.x;
    if (tid < H) { scs[tid] = sc[tid]; shs[tid] = sh[tid]; }
    __syncthreads();

    int rowBase = blockIdx.x * 128;

    // stage Wt: coalesced conflict-free copy of pre-transposed weights
    {
        const uint4* wsrc4 = (const uint4*)(g_wt + layer * H * H);
        uint4* wdst4 = (uint4*)Wt;
#pragma unroll
        for (int i = tid; i < 2048; i += 512) {
            int n = i >> 4, cc = i & 15;
            wdst4[n * 17 + cc] = wsrc4[i];  // 17 uint4 per padded row
        }
    }

    // stage A (BN+SiLU fused) in fp16
    for (int i = tid; i < 4096; i += 512) {
        int r = i >> 5, kq = (i & 31) * 4;
        int gr = rowBase + r;
        float4 pre;
        if (gr < N) {
            if (MODE == 0) {
                float xin = g_s[gr];
                pre.x = fmaf(xin, scs[kq + 0], shs[kq + 0]);
                pre.y = fmaf(xin, scs[kq + 1], shs[kq + 1]);
                pre.z = fmaf(xin, scs[kq + 2], shs[kq + 2]);
                pre.w = fmaf(xin, scs[kq + 3], shs[kq + 3]);
            } else {
                float4 xin = __ldg((const float4*)(SRC + (size_t)gr * H + kq));
                pre.x = fmaf(xin.x, scs[kq + 0], shs[kq + 0]);
                pre.y = fmaf(xin.y, scs[kq + 1], shs[kq + 1]);
                pre.z = fmaf(xin.z, scs[kq + 2], shs[kq + 2]);
                pre.w = fmaf(xin.w, scs[kq + 3], shs[kq + 3]);
            }
            pre.x = silu_t(pre.x);
            pre.y = silu_t(pre.y);
            pre.z = silu_t(pre.z);
            pre.w = silu_t(pre.w);
        } else {
            pre = make_float4(0.f, 0.f, 0.f, 0.f);
        }
        __half2* dst = (__half2*)(As + r * ASTRIDE + kq);
        dst[0] = __floats2half2_rn(pre.x, pre.y);
        dst[1] = __floats2half2_rn(pre.z, pre.w);
    }
    __syncthreads();

    int warp = tid >> 5, lane = tid & 31;
    int g = lane >> 2, tig = lane & 3;
    int rbase = (warp >> 1) * 16;
    int colbase = (warp & 1) * 64;

    unsigned asu = (unsigned)__cvta_generic_to_shared(As);
    unsigned wtu = (unsigned)__cvta_generic_to_shared(Wt);
    int rowA = rbase + ((lane >> 3) & 1) * 8 + (lane & 7);
    int colA = (lane >> 4) * 8;
    unsigned aAddr = asu + (unsigned)((rowA * ASTRIDE + colA) * 2);
    int nrowB = colbase + (lane >> 4) * 8 + (lane & 7);
    int colB = ((lane >> 3) & 1) * 8;
    unsigned bAddr = wtu + (unsigned)((nrowB * ASTRIDE + colB) * 2);

    float c[8][4];
#pragma unroll
    for (int j = 0; j < 8; j++)
#pragma unroll
        for (int q = 0; q < 4; q++) c[j][q] = 0.f;

#pragma unroll
    for (int k0 = 0; k0 < 128; k0 += 16) {
        unsigned a0, a1, a2, a3;
        ldsm4(a0, a1, a2, a3, aAddr + k0 * 2);
#pragma unroll
        for (int jj = 0; jj < 4; jj++) {
            unsigned b0, b1, b2, b3;
            ldsm4(b0, b1, b2, b3,
                  bAddr + (unsigned)(jj * (16 * ASTRIDE * 2) + k0 * 2));
            mma16816(c[2 * jj][0], c[2 * jj][1], c[2 * jj][2], c[2 * jj][3],
                     a0, a1, a2, a3, b0, b1);
            mma16816(c[2 * jj + 1][0], c[2 * jj + 1][1], c[2 * jj + 1][2],
                     c[2 * jj + 1][3], a0, a1, a2, a3, b2, b3);
        }
    }

    // epilogue: th[row] = half(dis[row] * out), 64 cols per warp
    int r0 = rowBase + rbase + g;
    int r1 = r0 + 8;
    float d0 = (r0 < N) ? __ldg(&g_dis[r0]) : 0.f;
    float d1 = (r1 < N) ? __ldg(&g_dis[r1]) : 0.f;
    __half* out0 = g_th + (size_t)r0 * H + colbase + 2 * tig;
    __half* out1 = g_th + (size_t)r1 * H + colbase + 2 * tig;
#pragma unroll
    for (int j = 0; j < 8; j++) {
        if (r0 < N)
            *(__half2*)(out0 + j * 8) = __floats2half2_rn(c[j][0] * d0, c[j][1] * d0);
        if (r1 < N)
            *(__half2*)(out1 + j * 8) = __floats2half2_rn(c[j][2] * d1, c[j][3] * d1);
    }
}

// ---------------------------------------------------------------------------
// gather: agg[c] = dis[c]*(tS[c] + sum_e tS[r]);  BN stats fused.
// One node per warp; rows accumulated IN FP16 via HADD2 (2 instr/row),
// converted to fp32 once per node. fp16 sum noise (~1e-3 pre-BN worst case)
// is same scale as existing message quantization; BN renormalizes.
// ---------------------------------------------------------------------------
__global__ void __launch_bounds__(256) gather_kernel(int N) {
    int lane = threadIdx.x & 31;
    int gw = blockIdx.x * 8 + (threadIdx.x >> 5);
    int nw = gridDim.x * 8;

    float4 lsum = make_float4(0.f, 0.f, 0.f, 0.f);
    float4 lsq = make_float4(0.f, 0.f, 0.f, 0.f);

    for (int c = gw; c < N; c += nw) {
        int beg = __ldg(&g_rowptr[c]);
        int end = beg + __ldg(&g_indeg[c]);
        float disc = __ldg(&g_dis[c]);
        uint2 sraw = __ldg(((const uint2*)(g_th + (size_t)c * H)) + lane);
        __half2 accL = *(__half2*)&sraw.x;
        __half2 accH = *(__half2*)&sraw.y;
        int e = beg;
        for (; e + 4 <= end; e += 4) {
            int r0 = __ldg(&g_csr[e + 0]);
            int r1 = __ldg(&g_csr[e + 1]);
            int r2 = __ldg(&g_csr[e + 2]);
            int r3 = __ldg(&g_csr[e + 3]);
            uint2 a0 = __ldg(((const uint2*)(g_th + (size_t)r0 * H)) + lane);
            uint2 a1 = __ldg(((const uint2*)(g_th + (size_t)r1 * H)) + lane);
            uint2 a2 = __ldg(((const uint2*)(g_th + (size_t)r2 * H)) + lane);
            uint2 a3 = __ldg(((const uint2*)(g_th + (size_t)r3 * H)) + lane);
            accL = __hadd2(accL, *(__half2*)&a0.x);
            accH = __hadd2(accH, *(__half2*)&a0.y);
            accL = __hadd2(accL, *(__half2*)&a1.x);
            accH = __hadd2(accH, *(__half2*)&a1.y);
            accL = __hadd2(accL, *(__half2*)&a2.x);
            accH = __hadd2(accH, *(__half2*)&a2.y);
            accL = __hadd2(accL, *(__half2*)&a3.x);
            accH = __hadd2(accH, *(__half2*)&a3.y);
        }
        for (; e < end; e++) {
            int r0 = __ldg(&g_csr[e]);
            uint2 a0 = __ldg(((const uint2*)(g_th + (size_t)r0 * H)) + lane);
            accL = __hadd2(accL, *(__half2*)&a0.x);
            accH = __hadd2(accH, *(__half2*)&a0.y);
        }
        float2 lo = __half22float2(accL);
        float2 hi = __half22float2(accH);
        float4 acc = make_float4(lo.x * disc, lo.y * disc, hi.x * disc, hi.y * disc);
        ((float4*)(g_agg + (size_t)c * H))[lane] = acc;
        lsum.x += acc.x; lsum.y += acc.y; lsum.z += acc.z; lsum.w += acc.w;
        lsq.x += acc.x * acc.x; lsq.y += acc.y * acc.y;
        lsq.z += acc.z * acc.z; lsq.w += acc.w * acc.w;
    }

    __shared__ float ssum[H], ssq[H];
    if (threadIdx.x < H) { ssum[threadIdx.x] = 0.f; ssq[threadIdx.x] = 0.f; }
    __syncthreads();
    int f = lane * 4;
    atomicAdd(&ssum[f + 0], lsum.x);
    atomicAdd(&ssum[f + 1], lsum.y);
    atomicAdd(&ssum[f + 2], lsum.z);
    atomicAdd(&ssum[f + 3], lsum.w);
    atomicAdd(&ssq[f + 0], lsq.x);
    atomicAdd(&ssq[f + 1], lsq.y);
    atomicAdd(&ssq[f + 2], lsq.z);
    atomicAdd(&ssq[f + 3], lsq.w);
    __syncthreads();
    if (threadIdx.x < H) {
        atomicAdd(&g_dsum[threadIdx.x], (double)ssum[threadIdx.x]);
        atomicAdd(&g_dsq[threadIdx.x], (double)ssq[threadIdx.x]);
    }
}

// ---------------------------------------------------------------------------
// finalize BN params; zero stats for next layer
// ---------------------------------------------------------------------------
__global__ void finalize_kernel(const float* __restrict__ gamma,
                                const float* __restrict__ beta, int N) {
    int f = threadIdx.x;
    if (f >= H) return;
    double mu = g_dsum[f] / N;
    double var = g_dsq[f] / N - mu * mu;
    g_dsum[f] = 0.0;
    g_dsq[f] = 0.0;
    float inv = rsqrtf((float)var + 1e-5f);
    float s = gamma[f] * inv;
    g_scale[f] = s;
    g_shift[f] = beta[f] - (float)mu * s;
}

// ---------------------------------------------------------------------------
// pooling (fuses BN+SiLU of last layer; exploits sorted batch ids)
// ---------------------------------------------------------------------------
__global__ void pool_kernel(const void* batch, int N) {
    const float* A = g_agg;
    int f = threadIdx.x;  // blockDim = 128
    float sc = g_scale[f], sh = g_shift[f];
    int rowsPer = (N + gridDim.x - 1) / gridDim.x;
    int r0 = blockIdx.x * rowsPer;
    int r1 = min(N, r0 + rowsPer);
    int is64 = g_is64;
    int curG = -1;
    float acc = 0.f, cacc = 0.f;
    for (int r = r0; r < r1; r++) {
        int g = ldidx(batch, r, is64);
        if (g != curG) {
            if (curG >= 0) {
                atomicAdd(&g_pool[curG * H + f], acc);
                if (f == 0) atomicAdd(&g_cnt[curG], cacc);
            }
            curG = g;
            acc = 0.f;
            cacc = 0.f;
        }
        float v = fmaf(__ldg(&A[(size_t)r * H + f]), sc, sh);
        acc += silu_t(v);
        cacc += 1.f;
    }
    if (curG >= 0) {
        atomicAdd(&g_pool[curG * H + f], acc);
        if (f == 0) atomicAdd(&g_cnt[curG], cacc);
    }
}

// ---------------------------------------------------------------------------
// MLP head
// ---------------------------------------------------------------------------
__global__ void mlp_kernel(const float* __restrict__ fc1w,
                           const float* __restrict__ fc1b,
                           const float* __restrict__ fc2w,
                           const float* __restrict__ fc2b, float* __restrict__ out,
                           int G) {
    int g = blockIdx.x;
    if (g >= G) return;
    int t = threadIdx.x;  // 64 threads
    __shared__ float p[H];
    __shared__ float invc_s;
    __shared__ float warpsum[2];
    if (t == 0) invc_s = __fdividef(1.f, fmaxf(g_cnt[g], 1.f));
    __syncthreads();
    float invc = invc_s;
    p[t] = g_pool[g * H + t] * invc;
    p[t + 64] = g_pool[g * H + t + 64] * invc;
    __syncthreads();
    float acc = fc1b[t];
#pragma unroll
    for (int k = 0; k < H; k++) acc = fmaf(p[k], fc1w[k * 64 + t], acc);
    float z = silu_t(acc);
    float part = z * fc2w[t];
#pragma unroll
    for (int off = 16; off > 0; off >>= 1)
        part += __shfl_down_sync(0xffffffffu, part, off);
    if ((t & 31) == 0) warpsum[t >> 5] = part;
    __syncthreads();
    if (t == 0) {
        float sum = warpsum[0] + warpsum[1] + fc2b[0];
        out[g] = __fdividef(1.f, 1.f + __expf(-sum));
    }
}

// ---------------------------------------------------------------------------
// host
// ---------------------------------------------------------------------------
static inline int nblk(long long n, int t) { return (int)((n + t - 1) / t); }

extern "C" void kernel_launch(void* const* d_in, const int* in_sizes, int n_in,
                              void* d_out, int out_size) {
    int N = in_sizes[0];
    int E = in_sizes[1] / 2;
    int base = (in_sizes[3] == 1) ? 4 : 3;

    const float* x = (const float*)d_in[0];
    const void* ei = d_in[1];
    const void* batch = d_in[2];
    const float* W0 = (const float*)d_in[base + 0];
    const float* Ws = (const float*)d_in[base + 1];
    // biases (base+2) cancel exactly inside BatchNorm -> unused
    const float* gammas = (const float*)d_in[base + 3];
    const float* betas = (const float*)d_in[base + 4];
    const float* fc1w = (const float*)d_in[base + 5];
    const float* fc1b = (const float*)d_in[base + 6];
    const float* fc2w = (const float*)d_in[base + 7];
    const float* fc2b = (const float*)d_in[base + 8];
    float* out = (float*)d_out;
    int G = out_size;

    cudaFuncSetAttribute(gemm_kernel<0>, cudaFuncAttributeMaxDynamicSharedMemorySize,
                         GEMM_SMEM_BYTES);
    cudaFuncSetAttribute(gemm_kernel<1>, cudaFuncAttributeMaxDynamicSharedMemorySize,
                         GEMM_SMEM_BYTES);

    int GP = G * H;
    long long initSpan = (long long)N;
    if (GP > initSpan) initSpan = GP;
    if (3 * H * H > initSpan) initSpan = 3 * H * H;
    int gB = nblk(N, 128);
    int gatherB = 1184;  // 8 blocks x 148 SMs

    // prep (wprep fused into init)
    init_kernel<<<nblk(initSpan, 256), 256>>>(ei, Ws, N, GP, G);
    indeg_count_kernel<<<nblk(E, 256), 256>>>(ei, E);
    assign_kernel<<<nblk(N, 256), 256>>>(x, N);
    fill_kernel<<<nblk(E, 256), 256>>>(ei, E);

    // layer 0 (rank-1 scalar path)
    layer0_kernel<<<nblk(N, 256), 256>>>(N);
    coef0_kernel<<<1, 128>>>(W0, gammas, betas, N);

    // layer 1
    gemm_kernel<0><<<gB, 512, GEMM_SMEM_BYTES>>>(0, N);
    gather_kernel<<<gatherB, 256>>>(N);
    finalize_kernel<<<1, 128>>>(gammas + H, betas + H, N);

    // layer 2
    gemm_kernel<1><<<gB, 512, GEMM_SMEM_BYTES>>>(1, N);
    gather_kernel<<<gatherB, 256>>>(N);
    finalize_kernel<<<1, 128>>>(gammas + 2 * H, betas + 2 * H, N);

    // layer 3
    gemm_kernel<1><<<gB, 512, GEMM_SMEM_BYTES>>>(2, N);
    gather_kernel<<<gatherB, 256>>>(N);
    finalize_kernel<<<1, 128>>>(gammas + 3 * H, betas + 3 * H, N);

    // pooling + head
    pool_kernel<<<1024, 128>>>(batch, N);
    mlp_kernel<<<G, 64>>>(fc1w, fc1b, fc2w, fc2b, out, G);
}

// round 17
// speedup vs baseline: 1.3644x; 1.1823x over previous
#include <cuda_runtime.h>
#include <cuda_fp16.h>
#include <math.h>

// ============================================================================
// SurfaceCodeGNN: 4-layer GCN + BN/SiLU + mean-pool + MLP head
// N=100000, E=600000, H=128, G=256
//
// Round 17: persistent GEMM (grid=296, W staged once per block, loop over
// row tiles -> no ragged wave, 486 fewer W stagings) + agg stored in fp16
// (halves agg-buffer L2 traffic in gather-store/GEMM-load/pool-load).
// Gather/layer0/prep as R16 (best = 312.4us).
// ============================================================================

#define H 128
#define MAXN 100352
#define MAXE 1200000
#define MAXG 1024

__device__ __half g_th[(size_t)MAXN * H];    // pre-scaled messages dis[r]*t[r]
__device__ __half g_aggh[(size_t)MAXN * H];  // gather output (pre-BN, fp16)
__device__ __half g_wt[3 * H * H];           // W transposed [layer][n][k] fp16
__device__ float  g_s[MAXN];
__device__ float  g_sx[MAXN];                // dis[i]*x[i]
__device__ float  g_dis[MAXN];
__device__ int    g_indeg[MAXN];
__device__ int    g_rowptr[MAXN];
__device__ int    g_cursor[MAXN];
__device__ int    g_csr[MAXE];
__device__ int    g_ctr;
__device__ double g_dsum[H], g_dsq[H];
__device__ double g_sstats[2];
__device__ float  g_scale[H], g_shift[H];
__device__ float  g_C0[H], g_B0[H];
__device__ float  g_pool[MAXG * H];
__device__ float  g_cnt[MAXG];
__device__ int    g_is64;

static __device__ __forceinline__ float silu_f(float x) {
    float e = __expf(-x);
    return __fdividef(x, 1.0f + e);
}

// silu via single-MUFU hw tanh: x*sigmoid(x) = 0.5x + 0.5x*tanh(x/2)
static __device__ __forceinline__ float silu_t(float x) {
    float t;
    asm("tanh.approx.f32 %0, %1;" : "=f"(t) : "f"(0.5f * x));
    return fmaf(0.5f * x, t, 0.5f * x);
}

static __device__ __forceinline__ int ldidx(const void* p, long long i, int is64) {
    return ((const int*)p)[is64 ? 2 * i : i];
}

// ---------------------------------------------------------------------------
// init: zero indeg/pool/cnt/counters; transpose W to fp16 n-major; detect
// index dtype. (3*H*H = 49152 < N so the i-span covers the transpose.)
// ---------------------------------------------------------------------------
__global__ void init_kernel(const void* ei, const float* __restrict__ Ws,
                            int N, int GP, int G) {
    int i = blockIdx.x * blockDim.x + threadIdx.x;
    if (i < N) g_indeg[i] = 0;
    if (i < GP) g_pool[i] = 0.f;
    if (i < G) g_cnt[i] = 0.f;
    if (i < 3 * H * H) {
        int layer = i >> 14;
        int rem = i & 16383;
        int k = rem >> 7, n = rem & 127;
        g_wt[layer * H * H + n * H + k] = __float2half_rn(Ws[i]);
    }
    if (i == 0) {
        g_ctr = 0;
        g_sstats[0] = 0.0;
        g_sstats[1] = 0.0;
    }
    if (blockIdx.x == 0 && threadIdx.x < 32) {
        int any = 0;
        const int* p = (const int*)ei;
        for (int k = threadIdx.x; k < 64; k += 32)
            if (p[2 * k + 1] != 0) any = 1;
        any = __any_sync(0xffffffffu, any);
        if (threadIdx.x == 0) g_is64 = any ? 0 : 1;
    }
}

__global__ void indeg_count_kernel(const void* ei, int E) {
    int e = blockIdx.x * blockDim.x + threadIdx.x;
    if (e >= E) return;
    int is64 = g_is64;
    int c = ldidx(ei, (long long)E + e, is64);
    atomicAdd(&g_indeg[c], 1);
}

// ---------------------------------------------------------------------------
// assign: dis, sx = dis*x, rowptr via warp-aggregated atomic (unpadded)
// ---------------------------------------------------------------------------
__global__ void assign_kernel(const float* __restrict__ x, int N) {
    int i = blockIdx.x * blockDim.x + threadIdx.x;
    int lane = threadIdx.x & 31;
    int deg = (i < N) ? g_indeg[i] : 0;
    int v = deg;
#pragma unroll
    for (int off = 1; off < 32; off <<= 1) {
        int t = __shfl_up_sync(0xffffffffu, v, off);
        if (lane >= off) v += t;
    }
    int warpTot = __shfl_sync(0xffffffffu, v, 31);
    int base = 0;
    if (lane == 31) base = atomicAdd(&g_ctr, warpTot);
    base = __shfl_sync(0xffffffffu, base, 31);
    if (i < N) {
        int rp = base + v - deg;
        g_rowptr[i] = rp;
        g_cursor[i] = rp;
        float dis = rsqrtf((float)(deg + 1));  // +1 self loop
        g_dis[i] = dis;
        g_sx[i] = dis * x[i];
    }
}

__global__ void fill_kernel(const void* ei, int E) {
    int e = blockIdx.x * blockDim.x + threadIdx.x;
    if (e >= E) return;
    int is64 = g_is64;
    int r = ldidx(ei, e, is64);
    int c = ldidx(ei, (long long)E + e, is64);
    int p = atomicAdd(&g_cursor[c], 1);
    g_csr[p] = r;
}

// ---------------------------------------------------------------------------
// layer 0: s[c] = dis[c]*(sx[c] + sum_e sx[r]), + stats
// ---------------------------------------------------------------------------
__global__ void layer0_kernel(int N) {
    int i = blockIdx.x * blockDim.x + threadIdx.x;
    float sum = 0.f, sq = 0.f;
    if (i < N) {
        int beg = g_rowptr[i], cnt = g_indeg[i];
        float acc = g_sx[i];
        for (int e = beg; e < beg + cnt; e++) {
            int r = __ldg(&g_csr[e]);
            acc += __ldg(&g_sx[r]);
        }
        acc *= g_dis[i];
        g_s[i] = acc;
        sum = acc;
        sq = acc * acc;
    }
    __shared__ float sa[256], sb[256];
    sa[threadIdx.x] = sum;
    sb[threadIdx.x] = sq;
    __syncthreads();
    for (int off = 128; off > 0; off >>= 1) {
        if (threadIdx.x < off) {
            sa[threadIdx.x] += sa[threadIdx.x + off];
            sb[threadIdx.x] += sb[threadIdx.x + off];
        }
        __syncthreads();
    }
    if (threadIdx.x == 0) {
        atomicAdd(&g_sstats[0], (double)sa[0]);
        atomicAdd(&g_sstats[1], (double)sb[0]);
    }
}

__global__ void coef0_kernel(const float* __restrict__ W0,
                             const float* __restrict__ gamma0,
                             const float* __restrict__ beta0, int N) {
    int t = threadIdx.x;
    if (t >= H) return;
    g_dsum[t] = 0.0;
    g_dsq[t] = 0.0;
    double mu = g_sstats[0] / N;
    double var = g_sstats[1] / N - mu * mu;
    float w = W0[t];
    float inv = rsqrtf((float)var * w * w + 1e-5f);
    float c = w * inv * gamma0[t];
    g_C0[t] = c;
    g_B0[t] = beta0[t] - (float)mu * c;
}

// ---------------------------------------------------------------------------
// Persistent tensor-core GEMM: th = half( dis[n] * (silu_bn(A) @ W) )
// grid=296 (2 blocks/SM exactly), W staged ONCE per block, loop over
// 128-row tiles. 512 threads; warp w -> rows [(w>>1)*16,+16),
// cols [(w&1)*64,+64). mma.sync.m16n8k16 + ldmatrix.x4.
// ---------------------------------------------------------------------------
#define ASTRIDE 136  // halfs per padded row (272B -> ldmatrix conflict-free)
#define GEMM_SMEM_BYTES (34816 * 2 + 1024)

static __device__ __forceinline__ void mma16816(float& c0, float& c1, float& c2,
                                                float& c3, unsigned a0, unsigned a1,
                                                unsigned a2, unsigned a3,
                                                unsigned b0, unsigned b1) {
    asm volatile(
        "mma.sync.aligned.m16n8k16.row.col.f32.f16.f16.f32 "
        "{%0,%1,%2,%3}, {%4,%5,%6,%7}, {%8,%9}, {%0,%1,%2,%3};"
        : "+f"(c0), "+f"(c1), "+f"(c2), "+f"(c3)
        : "r"(a0), "r"(a1), "r"(a2), "r"(a3), "r"(b0), "r"(b1));
}

static __device__ __forceinline__ void ldsm4(unsigned& r0, unsigned& r1,
                                             unsigned& r2, unsigned& r3,
                                             unsigned addr) {
    asm volatile(
        "ldmatrix.sync.aligned.m8n8.x4.shared.b16 {%0,%1,%2,%3}, [%4];"
        : "=r"(r0), "=r"(r1), "=r"(r2), "=r"(r3)
        : "r"(addr));
}

template <int MODE>
__global__ void __launch_bounds__(512, 2)
gemm_kernel(int layer, int N, int nTiles) {
    extern __shared__ char smraw[];
    __half* As = (__half*)smraw;                  // [128][ASTRIDE]
    __half* Wt = (__half*)(smraw + 34816);        // [128][ASTRIDE] (n-major)
    float* scs = (float*)(smraw + 69632);         // 128
    float* shs = scs + 128;                       // 128

    const float* sc = (MODE == 0) ? g_C0 : g_scale;
    const float* sh = (MODE == 0) ? g_B0 : g_shift;

    int tid = threadIdx.x;
    if (tid < H) { scs[tid] = sc[tid]; shs[tid] = sh[tid]; }

    // stage Wt once: coalesced conflict-free copy of pre-transposed weights
    {
        const uint4* wsrc4 = (const uint4*)(g_wt + layer * H * H);
        uint4* wdst4 = (uint4*)Wt;
#pragma unroll
        for (int i = tid; i < 2048; i += 512) {
            int n = i >> 4, cc = i & 15;
            wdst4[n * 17 + cc] = wsrc4[i];  // 17 uint4 per padded row
        }
    }
    __syncthreads();

    int warp = tid >> 5, lane = tid & 31;
    int g = lane >> 2, tig = lane & 3;
    int rbase = (warp >> 1) * 16;
    int colbase = (warp & 1) * 64;

    unsigned asu = (unsigned)__cvta_generic_to_shared(As);
    unsigned wtu = (unsigned)__cvta_generic_to_shared(Wt);
    int rowA = rbase + ((lane >> 3) & 1) * 8 + (lane & 7);
    int colA = (lane >> 4) * 8;
    unsigned aAddr = asu + (unsigned)((rowA * ASTRIDE + colA) * 2);
    int nrowB = colbase + (lane >> 4) * 8 + (lane & 7);
    int colB = ((lane >> 3) & 1) * 8;
    unsigned bAddr = wtu + (unsigned)((nrowB * ASTRIDE + colB) * 2);

    for (int tile = blockIdx.x; tile < nTiles; tile += gridDim.x) {
        int rowBase = tile * 128;

        // stage A (BN+SiLU fused) in fp16
        for (int i = tid; i < 4096; i += 512) {
            int r = i >> 5, kq = (i & 31) * 4;
            int gr = rowBase + r;
            float4 pre;
            if (gr < N) {
                if (MODE == 0) {
                    float xin = g_s[gr];
                    pre.x = fmaf(xin, scs[kq + 0], shs[kq + 0]);
                    pre.y = fmaf(xin, scs[kq + 1], shs[kq + 1]);
                    pre.z = fmaf(xin, scs[kq + 2], shs[kq + 2]);
                    pre.w = fmaf(xin, scs[kq + 3], shs[kq + 3]);
                } else {
                    uint2 raw = __ldg((const uint2*)(g_aggh + (size_t)gr * H + kq));
                    float2 lo = __half22float2(*(__half2*)&raw.x);
                    float2 hi = __half22float2(*(__half2*)&raw.y);
                    pre.x = fmaf(lo.x, scs[kq + 0], shs[kq + 0]);
                    pre.y = fmaf(lo.y, scs[kq + 1], shs[kq + 1]);
                    pre.z = fmaf(hi.x, scs[kq + 2], shs[kq + 2]);
                    pre.w = fmaf(hi.y, scs[kq + 3], shs[kq + 3]);
                }
                pre.x = silu_t(pre.x);
                pre.y = silu_t(pre.y);
                pre.z = silu_t(pre.z);
                pre.w = silu_t(pre.w);
            } else {
                pre = make_float4(0.f, 0.f, 0.f, 0.f);
            }
            __half2* dst = (__half2*)(As + r * ASTRIDE + kq);
            dst[0] = __floats2half2_rn(pre.x, pre.y);
            dst[1] = __floats2half2_rn(pre.z, pre.w);
        }
        __syncthreads();

        float c[8][4];
#pragma unroll
        for (int j = 0; j < 8; j++)
#pragma unroll
            for (int q = 0; q < 4; q++) c[j][q] = 0.f;

#pragma unroll
        for (int k0 = 0; k0 < 128; k0 += 16) {
            unsigned a0, a1, a2, a3;
            ldsm4(a0, a1, a2, a3, aAddr + k0 * 2);
#pragma unroll
            for (int jj = 0; jj < 4; jj++) {
                unsigned b0, b1, b2, b3;
                ldsm4(b0, b1, b2, b3,
                      bAddr + (unsigned)(jj * (16 * ASTRIDE * 2) + k0 * 2));
                mma16816(c[2 * jj][0], c[2 * jj][1], c[2 * jj][2], c[2 * jj][3],
                         a0, a1, a2, a3, b0, b1);
                mma16816(c[2 * jj + 1][0], c[2 * jj + 1][1], c[2 * jj + 1][2],
                         c[2 * jj + 1][3], a0, a1, a2, a3, b2, b3);
            }
        }

        // epilogue: th[row] = half(dis[row] * out), 64 cols per warp
        int r0 = rowBase + rbase + g;
        int r1 = r0 + 8;
        float d0 = (r0 < N) ? __ldg(&g_dis[r0]) : 0.f;
        float d1 = (r1 < N) ? __ldg(&g_dis[r1]) : 0.f;
        __half* out0 = g_th + (size_t)r0 * H + colbase + 2 * tig;
        __half* out1 = g_th + (size_t)r1 * H + colbase + 2 * tig;
#pragma unroll
        for (int j = 0; j < 8; j++) {
            if (r0 < N)
                *(__half2*)(out0 + j * 8) =
                    __floats2half2_rn(c[j][0] * d0, c[j][1] * d0);
            if (r1 < N)
                *(__half2*)(out1 + j * 8) =
                    __floats2half2_rn(c[j][2] * d1, c[j][3] * d1);
        }
        __syncthreads();  // As reuse next tile
    }
}

// ---------------------------------------------------------------------------
// gather: aggh[c] = fp16( dis[c]*(tS[c] + sum_e tS[r]) );  BN stats fused.
// One node per warp; HADD2 fp16 accumulation (R16 form, at latency floor).
// ---------------------------------------------------------------------------
__global__ void __launch_bounds__(256) gather_kernel(int N) {
    int lane = threadIdx.x & 31;
    int gw = blockIdx.x * 8 + (threadIdx.x >> 5);
    int nw = gridDim.x * 8;

    float4 lsum = make_float4(0.f, 0.f, 0.f, 0.f);
    float4 lsq = make_float4(0.f, 0.f, 0.f, 0.f);

    for (int c = gw; c < N; c += nw) {
        int beg = __ldg(&g_rowptr[c]);
        int end = beg + __ldg(&g_indeg[c]);
        float disc = __ldg(&g_dis[c]);
        uint2 sraw = __ldg(((const uint2*)(g_th + (size_t)c * H)) + lane);
        __half2 accL = *(__half2*)&sraw.x;
        __half2 accH = *(__half2*)&sraw.y;
        int e = beg;
        for (; e + 4 <= end; e += 4) {
            int r0 = __ldg(&g_csr[e + 0]);
            int r1 = __ldg(&g_csr[e + 1]);
            int r2 = __ldg(&g_csr[e + 2]);
            int r3 = __ldg(&g_csr[e + 3]);
            uint2 a0 = __ldg(((const uint2*)(g_th + (size_t)r0 * H)) + lane);
            uint2 a1 = __ldg(((const uint2*)(g_th + (size_t)r1 * H)) + lane);
            uint2 a2 = __ldg(((const uint2*)(g_th + (size_t)r2 * H)) + lane);
            uint2 a3 = __ldg(((const uint2*)(g_th + (size_t)r3 * H)) + lane);
            accL = __hadd2(accL, *(__half2*)&a0.x);
            accH = __hadd2(accH, *(__half2*)&a0.y);
            accL = __hadd2(accL, *(__half2*)&a1.x);
            accH = __hadd2(accH, *(__half2*)&a1.y);
            accL = __hadd2(accL, *(__half2*)&a2.x);
            accH = __hadd2(accH, *(__half2*)&a2.y);
            accL = __hadd2(accL, *(__half2*)&a3.x);
            accH = __hadd2(accH, *(__half2*)&a3.y);
        }
        for (; e < end; e++) {
            int r0 = __ldg(&g_csr[e]);
            uint2 a0 = __ldg(((const uint2*)(g_th + (size_t)r0 * H)) + lane);
            accL = __hadd2(accL, *(__half2*)&a0.x);
            accH = __hadd2(accH, *(__half2*)&a0.y);
        }
        float2 lo = __half22float2(accL);
        float2 hi = __half22float2(accH);
        float4 acc = make_float4(lo.x * disc, lo.y * disc, hi.x * disc, hi.y * disc);
        uint2 outp;
        *(__half2*)&outp.x = __floats2half2_rn(acc.x, acc.y);
        *(__half2*)&outp.y = __floats2half2_rn(acc.z, acc.w);
        ((uint2*)(g_aggh + (size_t)c * H))[lane] = outp;
        lsum.x += acc.x; lsum.y += acc.y; lsum.z += acc.z; lsum.w += acc.w;
        lsq.x += acc.x * acc.x; lsq.y += acc.y * acc.y;
        lsq.z += acc.z * acc.z; lsq.w += acc.w * acc.w;
    }

    __shared__ float ssum[H], ssq[H];
    if (threadIdx.x < H) { ssum[threadIdx.x] = 0.f; ssq[threadIdx.x] = 0.f; }
    __syncthreads();
    int f = lane * 4;
    atomicAdd(&ssum[f + 0], lsum.x);
    atomicAdd(&ssum[f + 1], lsum.y);
    atomicAdd(&ssum[f + 2], lsum.z);
    atomicAdd(&ssum[f + 3], lsum.w);
    atomicAdd(&ssq[f + 0], lsq.x);
    atomicAdd(&ssq[f + 1], lsq.y);
    atomicAdd(&ssq[f + 2], lsq.z);
    atomicAdd(&ssq[f + 3], lsq.w);
    __syncthreads();
    if (threadIdx.x < H) {
        atomicAdd(&g_dsum[threadIdx.x], (double)ssum[threadIdx.x]);
        atomicAdd(&g_dsq[threadIdx.x], (double)ssq[threadIdx.x]);
    }
}

// ---------------------------------------------------------------------------
// finalize BN params; zero stats for next layer
// ---------------------------------------------------------------------------
__global__ void finalize_kernel(const float* __restrict__ gamma,
                                const float* __restrict__ beta, int N) {
    int f = threadIdx.x;
    if (f >= H) return;
    double mu = g_dsum[f] / N;
    double var = g_dsq[f] / N - mu * mu;
    g_dsum[f] = 0.0;
    g_dsq[f] = 0.0;
    float inv = rsqrtf((float)var + 1e-5f);
    float s = gamma[f] * inv;
    g_scale[f] = s;
    g_shift[f] = beta[f] - (float)mu * s;
}

// ---------------------------------------------------------------------------
// pooling (fuses BN+SiLU of last layer; exploits sorted batch ids)
// ---------------------------------------------------------------------------
__global__ void pool_kernel(const void* batch, int N) {
    int f = threadIdx.x;  // blockDim = 128
    float sc = g_scale[f], sh = g_shift[f];
    int rowsPer = (N + gridDim.x - 1) / gridDim.x;
    int r0 = blockIdx.x * rowsPer;
    int r1 = min(N, r0 + rowsPer);
    int is64 = g_is64;
    int curG = -1;
    float acc = 0.f, cacc = 0.f;
    for (int r = r0; r < r1; r++) {
        int g = ldidx(batch, r, is64);
        if (g != curG) {
            if (curG >= 0) {
                atomicAdd(&g_pool[curG * H + f], acc);
                if (f == 0) atomicAdd(&g_cnt[curG], cacc);
            }
            curG = g;
            acc = 0.f;
            cacc = 0.f;
        }
        float a = __half2float(g_aggh[(size_t)r * H + f]);
        float v = fmaf(a, sc, sh);
        acc += silu_t(v);
        cacc += 1.f;
    }
    if (curG >= 0) {
        atomicAdd(&g_pool[curG * H + f], acc);
        if (f == 0) atomicAdd(&g_cnt[curG], cacc);
    }
}

// ---------------------------------------------------------------------------
// MLP head
// ---------------------------------------------------------------------------
__global__ void mlp_kernel(const float* __restrict__ fc1w,
                           const float* __restrict__ fc1b,
                           const float* __restrict__ fc2w,
                           const float* __restrict__ fc2b, float* __restrict__ out,
                           int G) {
    int g = blockIdx.x;
    if (g >= G) return;
    int t = threadIdx.x;  // 64 threads
    __shared__ float p[H];
    __shared__ float invc_s;
    __shared__ float warpsum[2];
    if (t == 0) invc_s = __fdividef(1.f, fmaxf(g_cnt[g], 1.f));
    __syncthreads();
    float invc = invc_s;
    p[t] = g_pool[g * H + t] * invc;
    p[t + 64] = g_pool[g * H + t + 64] * invc;
    __syncthreads();
    float acc = fc1b[t];
#pragma unroll
    for (int k = 0; k < H; k++) acc = fmaf(p[k], fc1w[k * 64 + t], acc);
    float z = silu_t(acc);
    float part = z * fc2w[t];
#pragma unroll
    for (int off = 16; off > 0; off >>= 1)
        part += __shfl_down_sync(0xffffffffu, part, off);
    if ((t & 31) == 0) warpsum[t >> 5] = part;
    __syncthreads();
    if (t == 0) {
        float sum = warpsum[0] + warpsum[1] + fc2b[0];
        out[g] = __fdividef(1.f, 1.f + __expf(-sum));
    }
}

// ---------------------------------------------------------------------------
// host
// ---------------------------------------------------------------------------
static inline int nblk(long long n, int t) { return (int)((n + t - 1) / t); }

extern "C" void kernel_launch(void* const* d_in, const int* in_sizes, int n_in,
                              void* d_out, int out_size) {
    int N = in_sizes[0];
    int E = in_sizes[1] / 2;
    int base = (in_sizes[3] == 1) ? 4 : 3;

    const float* x = (const float*)d_in[0];
    const void* ei = d_in[1];
    const void* batch = d_in[2];
    const float* W0 = (const float*)d_in[base + 0];
    const float* Ws = (const float*)d_in[base + 1];
    // biases (base+2) cancel exactly inside BatchNorm -> unused
    const float* gammas = (const float*)d_in[base + 3];
    const float* betas = (const float*)d_in[base + 4];
    const float* fc1w = (const float*)d_in[base + 5];
    const float* fc1b = (const float*)d_in[base + 6];
    const float* fc2w = (const float*)d_in[base + 7];
    const float* fc2b = (const float*)d_in[base + 8];
    float* out = (float*)d_out;
    int G = out_size;

    cudaFuncSetAttribute(gemm_kernel<0>, cudaFuncAttributeMaxDynamicSharedMemorySize,
                         GEMM_SMEM_BYTES);
    cudaFuncSetAttribute(gemm_kernel<1>, cudaFuncAttributeMaxDynamicSharedMemorySize,
                         GEMM_SMEM_BYTES);

    int GP = G * H;
    long long initSpan = (long long)N;
    if (GP > initSpan) initSpan = GP;
    if (3 * H * H > initSpan) initSpan = 3 * H * H;
    int nTiles = nblk(N, 128);
    int gemmB = 296;     // 2 blocks/SM exactly (persistent)
    int gatherB = 1184;  // 8 blocks x 148 SMs

    // prep (wprep fused into init)
    init_kernel<<<nblk(initSpan, 256), 256>>>(ei, Ws, N, GP, G);
    indeg_count_kernel<<<nblk(E, 256), 256>>>(ei, E);
    assign_kernel<<<nblk(N, 256), 256>>>(x, N);
    fill_kernel<<<nblk(E, 256), 256>>>(ei, E);

    // layer 0 (rank-1 scalar path)
    layer0_kernel<<<nblk(N, 256), 256>>>(N);
    coef0_kernel<<<1, 128>>>(W0, gammas, betas, N);

    // layer 1
    gemm_kernel<0><<<gemmB, 512, GEMM_SMEM_BYTES>>>(0, N, nTiles);
    gather_kernel<<<gatherB, 256>>>(N);
    finalize_kernel<<<1, 128>>>(gammas + H, betas + H, N);

    // layer 2
    gemm_kernel<1><<<gemmB, 512, GEMM_SMEM_BYTES>>>(1, N, nTiles);
    gather_kernel<<<gatherB, 256>>>(N);
    finalize_kernel<<<1, 128>>>(gammas + 2 * H, betas + 2 * H, N);

    // layer 3
    gemm_kernel<1><<<gemmB, 512, GEMM_SMEM_BYTES>>>(2, N, nTiles);
    gather_kernel<<<gatherB, 256>>>(N);
    finalize_kernel<<<1, 128>>>(gammas + 3 * H, betas + 3 * H, N);

    // pooling + head
    pool_kernel<<<1024, 128>>>(batch, N);
    mlp_kernel<<<G, 64>>>(fc1w, fc1b, fc2w, fc2b, out, G);
}